// round 11
// baseline (speedup 1.0000x reference)
#include <cuda_runtime.h>
#include <cuda_fp16.h>
#include <math.h>

#define Bn    4
#define Sn    2048
#define Dn    1024
#define Hn    8
#define LRn   512
#define LRHn  64
#define SHDn  128
#define EXPn  2
#define Kn    4
#define CONVn 1042
#define NPROJ 1554
#define NPPAD 1664   // NPROJ padded to multiple of 128
#define BSn   8192   // B*S

typedef unsigned long long ull;
typedef unsigned int u32;

// ---------------- scratch (device globals; no runtime allocation) ----------------
__device__ float g_proj[BSn * NPROJ];
__device__ float g_xv[BSn * 1024];
__device__ float g_fv[BSn * 1024];
__device__ float g_scan[BSn * 1024];
__device__ float g_rin[BSn * Hn];
__device__ float g_cg[BSn * Hn];
// fp16 hi/lo operand splits
__device__ __align__(16) __half g_xh[BSn * Dn];
__device__ __align__(16) __half g_xl[BSn * Dn];
__device__ __align__(16) __half g_wh[NPPAD * Dn];
__device__ __align__(16) __half g_wl[NPPAD * Dn];
__device__ __align__(16) __half g_owh[Dn * LRn];
__device__ __align__(16) __half g_owl[Dn * LRn];
__device__ __align__(16) __half g_vh[BSn * LRn];
__device__ __align__(16) __half g_vl[BSn * LRn];

// ---------------- helpers ----------------
__device__ __forceinline__ float sigmoidf_(float x) {
    return __fdividef(1.f, 1.f + __expf(-x));
}
__device__ __forceinline__ float tanhf_(float x) {
    float t = __expf(-2.f * fabsf(x));
    float r = __fdividef(1.f - t, 1.f + t);
    return copysignf(r, x);
}
__device__ __forceinline__ float blk_sum256(float v, float* sbuf) {
    int lane = threadIdx.x & 31, wid = threadIdx.x >> 5;
#pragma unroll
    for (int off = 16; off; off >>= 1) v += __shfl_xor_sync(0xffffffffu, v, off);
    if (lane == 0) sbuf[wid] = v;
    __syncthreads();
    float tot = 0.f;
#pragma unroll
    for (int i = 0; i < 8; i++) tot += sbuf[i];
    __syncthreads();
    return tot;
}
__device__ __forceinline__ float blk_sum512(float v, float* sbuf /*>=16*/) {
    int lane = threadIdx.x & 31, wid = threadIdx.x >> 5;
#pragma unroll
    for (int off = 16; off; off >>= 1) v += __shfl_xor_sync(0xffffffffu, v, off);
    if (lane == 0) sbuf[wid] = v;
    __syncthreads();
    float tot = 0.f;
#pragma unroll
    for (int i = 0; i < 16; i++) tot += sbuf[i];
    __syncthreads();
    return tot;
}
__device__ __forceinline__ void cp_async16(void* smem, const void* gmem) {
    unsigned s = (unsigned)__cvta_generic_to_shared(smem);
    asm volatile("cp.async.cg.shared.global [%0], [%1], 16;\n" ::"r"(s), "l"(gmem));
}
__device__ __forceinline__ void cp_async16_s(u32 saddr, const void* gmem) {
    asm volatile("cp.async.cg.shared.global [%0], [%1], 16;\n" ::"r"(saddr), "l"(gmem));
}

// ---- packed fp32x2 ----
__device__ __forceinline__ ull ffma2(ull a, ull b, ull c) {
    ull d;
    asm("fma.rn.f32x2 %0, %1, %2, %3;" : "=l"(d) : "l"(a), "l"(b), "l"(c));
    return d;
}
__device__ __forceinline__ ull pk2(float x, float y) {
    ull r;
    asm("mov.b64 %0, {%1, %2};" : "=l"(r) : "f"(x), "f"(y));
    return r;
}
__device__ __forceinline__ float2 u2f(ull v) {
    float2 f;
    asm("mov.b64 {%0, %1}, %2;" : "=f"(f.x), "=f"(f.y) : "l"(v));
    return f;
}

// ---- fp16 mma m16n8k16 ----
__device__ __forceinline__ void mma_f16(float* d, const u32* a, const u32* b) {
    asm volatile(
        "mma.sync.aligned.m16n8k16.row.col.f32.f16.f16.f32 "
        "{%0,%1,%2,%3}, {%4,%5,%6,%7}, {%8,%9}, {%0,%1,%2,%3};"
        : "+f"(d[0]), "+f"(d[1]), "+f"(d[2]), "+f"(d[3])
        : "r"(a[0]), "r"(a[1]), "r"(a[2]), "r"(a[3]), "r"(b[0]), "r"(b[1]));
}

// ---------------- K0: all f32 -> fp16 hi/lo splits in one launch ----------------
#define NX (BSn * Dn)
#define NW (NPPAD * Dn)
#define NO (Dn * LRn)
__global__ __launch_bounds__(256) void cvt_all_kernel(const float* __restrict__ x,
                                                      const float* __restrict__ w_in,
                                                      const float* __restrict__ out_w) {
    int i = blockIdx.x * 256 + threadIdx.x;
    if (i < NX) {
        float v = x[i];
        __half h = __float2half_rn(v);
        g_xh[i] = h;
        g_xl[i] = __float2half_rn(v - __half2float(h));
        return;
    }
    int j = i - NX;
    if (j < NW) {
        float v = (j < NPROJ * Dn) ? w_in[j] : 0.f;
        __half h = __float2half_rn(v);
        g_wh[j] = h;
        g_wl[j] = __float2half_rn(v - __half2float(h));
        return;
    }
    int k2 = j - NW;
    if (k2 < NO) {
        float v = out_w[k2];
        __half h = __float2half_rn(v);
        g_owh[k2] = h;
        g_owl[k2] = __float2half_rn(v - __half2float(h));
    }
}

// ---------------- fp16-split tensor-core GEMM: C[M,N] = A @ B^T ----------------
#define TCM 128
#define TCN 128
#define TCKC 32
#define WROW 20
#define LVL_W (128 * WROW)
#define BUF_W (4 * LVL_W)
#define TC_SMEM_DYN (2 * BUF_W * 4) // 81920 bytes

__global__ __launch_bounds__(256) void h2s_gemm_nt(const __half* __restrict__ Ah,
                                                   const __half* __restrict__ Al,
                                                   const __half* __restrict__ Bh,
                                                   const __half* __restrict__ Bl,
                                                   float* __restrict__ C,
                                                   int M, int N, int Kd) {
    extern __shared__ u32 sm[];
    int tid = threadIdx.x;
    int wid = tid >> 5, lane = tid & 31;
    int g = lane >> 2, t = lane & 3;
    int wm = (wid >> 2) * 64, wn = (wid & 3) * 32;
    int m0 = blockIdx.y * TCM, n0 = blockIdx.x * TCN;

    u32 sbase = (u32)__cvta_generic_to_shared(sm);

    const __half* srcA_h = Ah + (size_t)m0 * Kd;
    const __half* srcA_l = Al + (size_t)m0 * Kd;
    const __half* srcB_h = Bh + (size_t)n0 * Kd;
    const __half* srcB_l = Bl + (size_t)n0 * Kd;

    float acc[4][4][4];
#pragma unroll
    for (int i = 0; i < 4; i++)
#pragma unroll
        for (int j = 0; j < 4; j++)
#pragma unroll
            for (int q = 0; q < 4; q++) acc[i][j][q] = 0.f;

    int row2 = tid >> 2, j4 = tid & 3;
    const int nchunks = Kd / TCKC;

#define ISSUE_CHUNK(ck, buf) do {                                              \
        int k0_ = (ck) * TCKC;                                                 \
        u32 b_ = sbase + (buf) * BUF_W * 4;                                    \
        const __half* s0;                                                      \
        s0 = srcA_h + (size_t)row2 * Kd + k0_ + j4 * 8;                        \
        cp_async16_s(b_ + (0 * LVL_W + row2 * WROW + j4 * 4) * 4, s0);         \
        cp_async16_s(b_ + (0 * LVL_W + (row2 + 64) * WROW + j4 * 4) * 4,       \
                     s0 + (size_t)64 * Kd);                                    \
        s0 = srcA_l + (size_t)row2 * Kd + k0_ + j4 * 8;                        \
        cp_async16_s(b_ + (1 * LVL_W + row2 * WROW + j4 * 4) * 4, s0);         \
        cp_async16_s(b_ + (1 * LVL_W + (row2 + 64) * WROW + j4 * 4) * 4,       \
                     s0 + (size_t)64 * Kd);                                    \
        s0 = srcB_h + (size_t)row2 * Kd + k0_ + j4 * 8;                        \
        cp_async16_s(b_ + (2 * LVL_W + row2 * WROW + j4 * 4) * 4, s0);         \
        cp_async16_s(b_ + (2 * LVL_W + (row2 + 64) * WROW + j4 * 4) * 4,       \
                     s0 + (size_t)64 * Kd);                                    \
        s0 = srcB_l + (size_t)row2 * Kd + k0_ + j4 * 8;                        \
        cp_async16_s(b_ + (3 * LVL_W + row2 * WROW + j4 * 4) * 4, s0);         \
        cp_async16_s(b_ + (3 * LVL_W + (row2 + 64) * WROW + j4 * 4) * 4,       \
                     s0 + (size_t)64 * Kd);                                    \
        asm volatile("cp.async.commit_group;");                                \
    } while (0)

    ISSUE_CHUNK(0, 0);

    for (int ck = 0; ck < nchunks; ck++) {
        int cur = ck & 1;
        bool has_next = (ck + 1 < nchunks);
        if (has_next) {
            ISSUE_CHUNK(ck + 1, cur ^ 1);
            asm volatile("cp.async.wait_group 1;");
        } else {
            asm volatile("cp.async.wait_group 0;");
        }
        __syncthreads();

        const u32* SAh = sm + cur * BUF_W;
        const u32* SAl = SAh + LVL_W;
        const u32* SBh = SAh + 2 * LVL_W;
        const u32* SBl = SAh + 3 * LVL_W;

#pragma unroll
        for (int ks = 0; ks < 2; ks++) {
            int ko = ks * 8;
            u32 bh[4][2], bl[4][2];
#pragma unroll
            for (int nt = 0; nt < 4; nt++) {
                int rb = (wn + nt * 8 + g) * WROW + ko + t;
                bh[nt][0] = SBh[rb]; bh[nt][1] = SBh[rb + 4];
                bl[nt][0] = SBl[rb]; bl[nt][1] = SBl[rb + 4];
            }
#pragma unroll
            for (int mt = 0; mt < 4; mt++) {
                int r0 = (wm + mt * 16 + g) * WROW + ko + t;
                int r8 = r0 + 8 * WROW;
                u32 ah[4], al[4];
                ah[0] = SAh[r0]; ah[1] = SAh[r8];
                ah[2] = SAh[r0 + 4]; ah[3] = SAh[r8 + 4];
                al[0] = SAl[r0]; al[1] = SAl[r8];
                al[2] = SAl[r0 + 4]; al[3] = SAl[r8 + 4];
#pragma unroll
                for (int nt = 0; nt < 4; nt++) {
                    mma_f16(acc[mt][nt], ah, bh[nt]);   // hi*hi (exact in fp32)
                    mma_f16(acc[mt][nt], ah, bl[nt]);   // hi*lo
                    mma_f16(acc[mt][nt], al, bh[nt]);   // lo*hi
                }
            }
        }
        __syncthreads();
    }

#pragma unroll
    for (int mt = 0; mt < 4; mt++) {
#pragma unroll
        for (int nt = 0; nt < 4; nt++) {
            int r = m0 + wm + mt * 16 + g;
            int c = n0 + wn + nt * 8 + t * 2;
            if (c + 1 < N) {
                *(float2*)(C + (size_t)r * N + c) =
                    make_float2(acc[mt][nt][0], acc[mt][nt][1]);
                *(float2*)(C + (size_t)(r + 8) * N + c) =
                    make_float2(acc[mt][nt][2], acc[mt][nt][3]);
            } else if (c < N) {
                C[(size_t)r * N + c] = acc[mt][nt][0];
                C[(size_t)(r + 8) * N + c] = acc[mt][nt][2];
            }
        }
    }
}

// ---------------- K2: fused conv+silu+norms+expand -> xv, fv, rin, cg ----------------
__global__ __launch_bounds__(256) void convbuild_kernel(const float* __restrict__ conv_w,
                                                        const float* __restrict__ w_in_norm,
                                                        const float* __restrict__ w_f_norm,
                                                        const float* __restrict__ w_r_norm) {
    __shared__ float sy[CONVn];
    __shared__ float sb1[8], sb2[8];
    __shared__ float srs[1];
    int row = blockIdx.x;      // b*S + s
    int s = row % Sn;
    int tid = threadIdx.x;

    // depthwise conv K=4 (causal) + silu, straight into smem
    const float* p0 = g_proj + (size_t)row * NPROJ;
    for (int c = tid; c < CONVn; c += 256) {
        float w0 = conv_w[c * 4 + 0], w1 = conv_w[c * 4 + 1];
        float w2 = conv_w[c * 4 + 2], w3 = conv_w[c * 4 + 3];
        float acc = w3 * p0[c];
        if (s >= 1) acc += w2 * p0[c - NPROJ];
        if (s >= 2) acc += w1 * p0[c - 2 * NPROJ];
        if (s >= 3) acc += w0 * p0[c - 3 * NPROJ];
        sy[c] = acc * sigmoidf_(acc);
    }
    __syncthreads();

    float s1 = 0.f, s2 = 0.f;
    for (int i = tid; i < 512; i += 256) {
        s1 += sy[i] * sy[i];
        s2 += sy[512 + i] * sy[512 + i];
    }
    float t1 = blk_sum256(s1, sb1);
    float t2 = blk_sum256(s2, sb2);
    if (tid == 0) {
        float sr = 0.f;
#pragma unroll
        for (int h = 0; h < 8; h++) sr += sy[1024 + h] * sy[1024 + h];
        srs[0] = rsqrtf(sr * (1.f / 8.f) + 1e-6f);
    }
    float si = rsqrtf(t1 * (1.f / 512.f) + 1e-6f);
    float sf = rsqrtf(t2 * (1.f / 512.f) + 1e-6f);
    __syncthreads();

    float e0 = sy[1040], e1 = sy[1041];
    float* xv = g_xv + (size_t)row * 1024;
    float* fv = g_fv + (size_t)row * 1024;
#pragma unroll
    for (int q = 0; q < 4; q++) {
        int o = tid + q * 256;
        int hh = o >> 7, rem = o & 127, ee = rem >> 6, dd = rem & 63;
        int ii = hh * 64 + dd;
        float ex = (ee == 0) ? e0 : e1;
        xv[o] = sy[ii] * si * w_in_norm[ii] * ex;
        fv[o] = sy[512 + ii] * sf * w_f_norm[ii] * ex;
    }
    if (tid < 8) {
        g_rin[(size_t)row * 8 + tid] = sy[1024 + tid] * srs[0] * w_r_norm[tid];
        g_cg[(size_t)row * 8 + tid] = sy[1032 + tid];
    }
}

// ---------------- K3: sequential recurrence, one CTA per (b,h), 512 threads ----------------
// 4 threads per column e (k-quarters); reductions via 2-level shfl_xor.
// state_w normalization fused into the prologue.
__global__ __launch_bounds__(512, 1) void scan_kernel(const float* __restrict__ state_w,
                                                      const float* __restrict__ res_w) {
    int b = blockIdx.x >> 3, hh = blockIdx.x & 7;
    int tid = threadIdx.x;
    int e = tid >> 2, q = tid & 3;

    __shared__ __align__(16) float h_sh[128];
    __shared__ __align__(16) float rh_sh[128];
    __shared__ __align__(16) float xbuf[2][128];
    __shared__ __align__(16) float fbuf[2][128];
    __shared__ float rin_s[Sn], cg_s[Sn];
    __shared__ float sbuf[16];

    // --- fused state_w normalization + packed weight load ---
    const float* bw = state_w + (size_t)hh * 16384 + (q * 32) * 128 + e;
    const float* bf = state_w + (size_t)(8 + hh) * 16384 + (q * 32) * 128 + e;
    const float* br = state_w + (size_t)(16 + hh) * 16384 + (q * 32) * 128 + e;
    float ssW = 0.f, ssF = 0.f, ssR = 0.f;
#pragma unroll 8
    for (int i = 0; i < 32; i++) {
        float vw = bw[i * 128], vf = bf[i * 128], vr = br[i * 128];
        ssW += vw * vw; ssF += vf * vf; ssR += vr * vr;
    }
    float totW = blk_sum512(ssW, sbuf);
    float totF = blk_sum512(ssF, sbuf);
    float totR = blk_sum512(ssR, sbuf);
    float invW = 1.f / fmaxf(sqrtf(totW), 1e-12f);
    float invF = 1.f / fmaxf(sqrtf(totF), 1e-12f);
    float invR = 1.f / fmaxf(sqrtf(totR), 1e-12f);

    ull W2[16], F2[16], R2[16];
#pragma unroll
    for (int i = 0; i < 16; i++) {
        W2[i] = pk2(bw[(2 * i) * 128] * invW, bw[(2 * i + 1) * 128] * invW);
        F2[i] = pk2(bf[(2 * i) * 128] * invF, bf[(2 * i + 1) * 128] * invF);
        R2[i] = pk2(br[(2 * i) * 128] * invR, br[(2 * i + 1) * 128] * invR);
    }

    for (int t = tid; t < Sn; t += 512) {
        rin_s[t] = g_rin[(size_t)(b * Sn + t) * 8 + hh];
        cg_s[t]  = g_cg[(size_t)(b * Sn + t) * 8 + hh];
    }
    if (tid < 128) h_sh[tid] = 0.f;
    float resw = res_w[hh];
    size_t rowbase = ((size_t)b * Sn) * 1024 + hh * 128;

    if (tid < 32)       cp_async16(&xbuf[0][tid * 4], g_xv + rowbase + tid * 4);
    else if (tid < 64)  cp_async16(&fbuf[0][(tid - 32) * 4], g_fv + rowbase + (tid - 32) * 4);
    asm volatile("cp.async.commit_group;");

    const ulonglong2* h4  = (const ulonglong2*)(h_sh)  + q * 8;   // 8 x ull2 = 32 floats
    const ulonglong2* rh4 = (const ulonglong2*)(rh_sh) + q * 8;

    for (int t = 0; t < Sn; t++) {
        int cur = t & 1, nxt = cur ^ 1;
        __syncthreads();   // S1: h_sh from prev step visible; nxt buffers free
        if (t + 1 < Sn) {
            size_t nb = rowbase + (size_t)(t + 1) * 1024;
            if (tid < 32)      cp_async16(&xbuf[nxt][tid * 4], g_xv + nb + tid * 4);
            else if (tid < 64) cp_async16(&fbuf[nxt][(tid - 32) * 4], g_fv + nb + (tid - 32) * 4);
        }
        asm volatile("cp.async.commit_group;");

        // Phase A: partial dots over this thread's k-quarter (chain depth 8)
        ull pR2 = 0ull, pF2 = 0ull;
#pragma unroll
        for (int i = 0; i < 8; i++) {
            ulonglong2 hv = h4[i];
            pR2 = ffma2(hv.x, R2[2 * i], pR2);
            pF2 = ffma2(hv.x, F2[2 * i], pF2);
            pR2 = ffma2(hv.y, R2[2 * i + 1], pR2);
            pF2 = ffma2(hv.y, F2[2 * i + 1], pF2);
        }
        float2 fR = u2f(pR2), fF = u2f(pF2);
        float pR = fR.x + fR.y, pF = fF.x + fF.y;
        pR += __shfl_xor_sync(0xffffffffu, pR, 1);
        pF += __shfl_xor_sync(0xffffffffu, pF, 1);
        pR += __shfl_xor_sync(0xffffffffu, pR, 2);
        pF += __shfl_xor_sync(0xffffffffu, pF, 2);

        if (q == 0) {
            float rv = sigmoidf_(rin_s[t] + pR);
            rh_sh[e] = rv * h_sh[e];
        }

        asm volatile("cp.async.wait_group 1;");
        __syncthreads();   // S2: rh_sh ready; cp.async data for t visible

        float fgate = 0.f;
        if (q == 3) fgate = sigmoidf_(fbuf[cur][e] + pF);

        // Phase B
        ull pW2 = 0ull;
#pragma unroll
        for (int i = 0; i < 8; i++) {
            ulonglong2 hv = rh4[i];
            pW2 = ffma2(hv.x, W2[2 * i], pW2);
            pW2 = ffma2(hv.y, W2[2 * i + 1], pW2);
        }
        float2 fW = u2f(pW2);
        float pW = fW.x + fW.y;
        pW += __shfl_xor_sync(0xffffffffu, pW, 1);
        pW += __shfl_xor_sync(0xffffffffu, pW, 2);

        if (q == 3) {
            float xt = xbuf[cur][e];
            float htl = tanhf_(xt + pW);
            float hn = fgate * h_sh[e] + (1.f - fgate) * htl;
            h_sh[e] = hn;
            g_scan[rowbase + (size_t)t * 1024 + e] = resw * xt + hn * cg_s[t];
        }
    }
}

// ---------------- K4: up-proj + gate silu + rms -> fp16 hi/lo v ----------------
__global__ __launch_bounds__(256) void ugate_kernel(const float* __restrict__ up_w,
                                                    const float* __restrict__ w_g_norm) {
    __shared__ float srow[1024];
    __shared__ float suw[64 * 129];
    __shared__ float sb[8];
    int row = blockIdx.x;
    int tid = threadIdx.x;

    const float* sr = g_scan + (size_t)row * 1024;
    for (int i = tid; i < 1024; i += 256) srow[i] = sr[i];
    for (int i = tid; i < 8192; i += 256) {
        int j = i >> 7, d = i & 127;
        suw[j * 129 + d] = up_w[i];
    }
    __syncthreads();

    int o0 = tid * 2, o1 = o0 + 1;
    int hhd = o0 >> 6;
    int j0 = o0 & 63, j1 = o1 & 63;
    const float* a = srow + hhd * 128;
    float acc0 = 0.f, acc1 = 0.f;
#pragma unroll 16
    for (int d = 0; d < 128; d++) {
        float av = a[d];
        acc0 += av * suw[j0 * 129 + d];
        acc1 += av * suw[j1 * 129 + d];
    }
    const float* gptr = g_proj + (size_t)row * NPROJ + CONVn;
    float gA = gptr[o0], gB = gptr[o1];
    float u0 = acc0 * (gA * sigmoidf_(gA));
    float u1 = acc1 * (gB * sigmoidf_(gB));

    float tot = blk_sum256(u0 * u0 + u1 * u1, sb);
    float scale = rsqrtf(tot * (1.f / 512.f) + 1e-6f);
    float v0 = u0 * scale * w_g_norm[o0];
    float v1 = u1 * scale * w_g_norm[o1];

    size_t ob = (size_t)row * 512;
    __half h0 = __float2half_rn(v0), h1 = __float2half_rn(v1);
    g_vh[ob + o0] = h0;
    g_vh[ob + o1] = h1;
    g_vl[ob + o0] = __float2half_rn(v0 - __half2float(h0));
    g_vl[ob + o1] = __float2half_rn(v1 - __half2float(h1));
}

// ---------------- launch ----------------
extern "C" void kernel_launch(void* const* d_in, const int* in_sizes, int n_in,
                              void* d_out, int out_size) {
    const float* x         = (const float*)d_in[0];
    const float* w_in      = (const float*)d_in[1];
    const float* conv_w    = (const float*)d_in[2];
    const float* state_w   = (const float*)d_in[3];
    const float* up_w      = (const float*)d_in[4];
    const float* out_w     = (const float*)d_in[5];
    const float* res_w     = (const float*)d_in[6];
    const float* w_in_norm = (const float*)d_in[7];
    const float* w_f_norm  = (const float*)d_in[8];
    const float* w_r_norm  = (const float*)d_in[9];
    const float* w_g_norm  = (const float*)d_in[10];
    float* out = (float*)d_out;

    float* p_proj = nullptr;
    cudaGetSymbolAddress((void**)&p_proj, g_proj);
    __half *p_xh, *p_xl, *p_wh, *p_wl, *p_owh, *p_owl, *p_vh, *p_vl;
    cudaGetSymbolAddress((void**)&p_xh, g_xh);
    cudaGetSymbolAddress((void**)&p_xl, g_xl);
    cudaGetSymbolAddress((void**)&p_wh, g_wh);
    cudaGetSymbolAddress((void**)&p_wl, g_wl);
    cudaGetSymbolAddress((void**)&p_owh, g_owh);
    cudaGetSymbolAddress((void**)&p_owl, g_owl);
    cudaGetSymbolAddress((void**)&p_vh, g_vh);
    cudaGetSymbolAddress((void**)&p_vl, g_vl);

    cudaFuncSetAttribute(h2s_gemm_nt, cudaFuncAttributeMaxDynamicSharedMemorySize,
                         TC_SMEM_DYN);

    // #1: all operand splits
    cvt_all_kernel<<<(NX + NW + NO + 255) / 256, 256>>>(x, w_in, out_w);
    // #2: proj = x @ w_in^T
    h2s_gemm_nt<<<dim3(NPPAD / TCN, BSn / TCM), 256, TC_SMEM_DYN>>>(
        p_xh, p_xl, p_wh, p_wl, p_proj, BSn, NPROJ, Dn);
    // #3: fused conv+silu+norms+expand
    convbuild_kernel<<<BSn, 256>>>(conv_w, w_in_norm, w_f_norm, w_r_norm);
    // #4: sequential scan (captured by ncu)
    scan_kernel<<<Bn * Hn, 512>>>(state_w, res_w);
    // #5: up-proj + gate + rms
    ugate_kernel<<<BSn, 256>>>(up_w, w_g_norm);
    // #6: final = v @ out_w^T
    h2s_gemm_nt<<<dim3(Dn / TCN, BSn / TCM), 256, TC_SMEM_DYN>>>(
        p_vh, p_vl, p_owh, p_owl, out, BSn, Dn, LRn);
}

// round 12
// speedup vs baseline: 2.7782x; 2.7782x over previous
#include <cuda_runtime.h>
#include <cuda_fp16.h>
#include <math.h>

#define Bn    4
#define Sn    2048
#define Dn    1024
#define Hn    8
#define LRn   512
#define LRHn  64
#define SHDn  128
#define EXPn  2
#define Kn    4
#define CONVn 1042
#define NPROJ 1554
#define NPPAD 1664   // NPROJ padded to multiple of 128
#define BSn   8192   // B*S

typedef unsigned long long ull;
typedef unsigned int u32;

// ---------------- scratch (device globals; no runtime allocation) ----------------
__device__ float g_proj[BSn * NPROJ];
__device__ float g_xv[BSn * 1024];
__device__ float g_fv[BSn * 1024];
__device__ float g_scan[BSn * 1024];
__device__ float g_rin[BSn * Hn];
__device__ float g_cg[BSn * Hn];
// fp16 hi/lo operand splits
__device__ __align__(16) __half g_xh[BSn * Dn];
__device__ __align__(16) __half g_xl[BSn * Dn];
__device__ __align__(16) __half g_wh[NPPAD * Dn];
__device__ __align__(16) __half g_wl[NPPAD * Dn];
__device__ __align__(16) __half g_owh[Dn * LRn];
__device__ __align__(16) __half g_owl[Dn * LRn];
__device__ __align__(16) __half g_vh[BSn * LRn];
__device__ __align__(16) __half g_vl[BSn * LRn];

// ---------------- helpers ----------------
__device__ __forceinline__ float sigmoidf_(float x) {
    return __fdividef(1.f, 1.f + __expf(-x));
}
__device__ __forceinline__ float tanhf_(float x) {
    float t = __expf(-2.f * fabsf(x));
    float r = __fdividef(1.f - t, 1.f + t);
    return copysignf(r, x);
}
__device__ __forceinline__ float blk_sum256(float v, float* sbuf) {
    int lane = threadIdx.x & 31, wid = threadIdx.x >> 5;
#pragma unroll
    for (int off = 16; off; off >>= 1) v += __shfl_xor_sync(0xffffffffu, v, off);
    if (lane == 0) sbuf[wid] = v;
    __syncthreads();
    float tot = 0.f;
#pragma unroll
    for (int i = 0; i < 8; i++) tot += sbuf[i];
    __syncthreads();
    return tot;
}
__device__ __forceinline__ void cp_async16(void* smem, const void* gmem) {
    unsigned s = (unsigned)__cvta_generic_to_shared(smem);
    asm volatile("cp.async.cg.shared.global [%0], [%1], 16;\n" ::"r"(s), "l"(gmem));
}
__device__ __forceinline__ void cp_async16_s(u32 saddr, const void* gmem) {
    asm volatile("cp.async.cg.shared.global [%0], [%1], 16;\n" ::"r"(saddr), "l"(gmem));
}

// ---- packed fp32x2 ----
__device__ __forceinline__ ull ffma2(ull a, ull b, ull c) {
    ull d;
    asm("fma.rn.f32x2 %0, %1, %2, %3;" : "=l"(d) : "l"(a), "l"(b), "l"(c));
    return d;
}
__device__ __forceinline__ ull pk2(float x, float y) {
    ull r;
    asm("mov.b64 %0, {%1, %2};" : "=l"(r) : "f"(x), "f"(y));
    return r;
}
__device__ __forceinline__ float2 u2f(ull v) {
    float2 f;
    asm("mov.b64 {%0, %1}, %2;" : "=f"(f.x), "=f"(f.y) : "l"(v));
    return f;
}

// ---- fp16 mma m16n8k16 ----
__device__ __forceinline__ void mma_f16(float* d, const u32* a, const u32* b) {
    asm volatile(
        "mma.sync.aligned.m16n8k16.row.col.f32.f16.f16.f32 "
        "{%0,%1,%2,%3}, {%4,%5,%6,%7}, {%8,%9}, {%0,%1,%2,%3};"
        : "+f"(d[0]), "+f"(d[1]), "+f"(d[2]), "+f"(d[3])
        : "r"(a[0]), "r"(a[1]), "r"(a[2]), "r"(a[3]), "r"(b[0]), "r"(b[1]));
}

// ---------------- K0: all f32 -> fp16 hi/lo splits in one launch ----------------
#define NX (BSn * Dn)
#define NW (NPPAD * Dn)
#define NO (Dn * LRn)
__global__ __launch_bounds__(256) void cvt_all_kernel(const float* __restrict__ x,
                                                      const float* __restrict__ w_in,
                                                      const float* __restrict__ out_w) {
    int i = blockIdx.x * 256 + threadIdx.x;
    if (i < NX) {
        float v = x[i];
        __half h = __float2half_rn(v);
        g_xh[i] = h;
        g_xl[i] = __float2half_rn(v - __half2float(h));
        return;
    }
    int j = i - NX;
    if (j < NW) {
        float v = (j < NPROJ * Dn) ? w_in[j] : 0.f;
        __half h = __float2half_rn(v);
        g_wh[j] = h;
        g_wl[j] = __float2half_rn(v - __half2float(h));
        return;
    }
    int k2 = j - NW;
    if (k2 < NO) {
        float v = out_w[k2];
        __half h = __float2half_rn(v);
        g_owh[k2] = h;
        g_owl[k2] = __float2half_rn(v - __half2float(h));
    }
}

// ---------------- fp16-split tensor-core GEMM: C[M,N] = A @ B^T ----------------
#define TCM 128
#define TCN 128
#define TCKC 32
#define WROW 20
#define LVL_W (128 * WROW)
#define BUF_W (4 * LVL_W)
#define TC_SMEM_DYN (2 * BUF_W * 4) // 81920 bytes

__global__ __launch_bounds__(256) void h2s_gemm_nt(const __half* __restrict__ Ah,
                                                   const __half* __restrict__ Al,
                                                   const __half* __restrict__ Bh,
                                                   const __half* __restrict__ Bl,
                                                   float* __restrict__ C,
                                                   int M, int N, int Kd) {
    extern __shared__ u32 sm[];
    int tid = threadIdx.x;
    int wid = tid >> 5, lane = tid & 31;
    int g = lane >> 2, t = lane & 3;
    int wm = (wid >> 2) * 64, wn = (wid & 3) * 32;
    int m0 = blockIdx.y * TCM, n0 = blockIdx.x * TCN;

    u32 sbase = (u32)__cvta_generic_to_shared(sm);

    const __half* srcA_h = Ah + (size_t)m0 * Kd;
    const __half* srcA_l = Al + (size_t)m0 * Kd;
    const __half* srcB_h = Bh + (size_t)n0 * Kd;
    const __half* srcB_l = Bl + (size_t)n0 * Kd;

    float acc[4][4][4];
#pragma unroll
    for (int i = 0; i < 4; i++)
#pragma unroll
        for (int j = 0; j < 4; j++)
#pragma unroll
            for (int q = 0; q < 4; q++) acc[i][j][q] = 0.f;

    int row2 = tid >> 2, j4 = tid & 3;
    const int nchunks = Kd / TCKC;

#define ISSUE_CHUNK(ck, buf) do {                                              \
        int k0_ = (ck) * TCKC;                                                 \
        u32 b_ = sbase + (buf) * BUF_W * 4;                                    \
        const __half* s0;                                                      \
        s0 = srcA_h + (size_t)row2 * Kd + k0_ + j4 * 8;                        \
        cp_async16_s(b_ + (0 * LVL_W + row2 * WROW + j4 * 4) * 4, s0);         \
        cp_async16_s(b_ + (0 * LVL_W + (row2 + 64) * WROW + j4 * 4) * 4,       \
                     s0 + (size_t)64 * Kd);                                    \
        s0 = srcA_l + (size_t)row2 * Kd + k0_ + j4 * 8;                        \
        cp_async16_s(b_ + (1 * LVL_W + row2 * WROW + j4 * 4) * 4, s0);         \
        cp_async16_s(b_ + (1 * LVL_W + (row2 + 64) * WROW + j4 * 4) * 4,       \
                     s0 + (size_t)64 * Kd);                                    \
        s0 = srcB_h + (size_t)row2 * Kd + k0_ + j4 * 8;                        \
        cp_async16_s(b_ + (2 * LVL_W + row2 * WROW + j4 * 4) * 4, s0);         \
        cp_async16_s(b_ + (2 * LVL_W + (row2 + 64) * WROW + j4 * 4) * 4,       \
                     s0 + (size_t)64 * Kd);                                    \
        s0 = srcB_l + (size_t)row2 * Kd + k0_ + j4 * 8;                        \
        cp_async16_s(b_ + (3 * LVL_W + row2 * WROW + j4 * 4) * 4, s0);         \
        cp_async16_s(b_ + (3 * LVL_W + (row2 + 64) * WROW + j4 * 4) * 4,       \
                     s0 + (size_t)64 * Kd);                                    \
        asm volatile("cp.async.commit_group;");                                \
    } while (0)

    ISSUE_CHUNK(0, 0);

    for (int ck = 0; ck < nchunks; ck++) {
        int cur = ck & 1;
        bool has_next = (ck + 1 < nchunks);
        if (has_next) {
            ISSUE_CHUNK(ck + 1, cur ^ 1);
            asm volatile("cp.async.wait_group 1;");
        } else {
            asm volatile("cp.async.wait_group 0;");
        }
        __syncthreads();

        const u32* SAh = sm + cur * BUF_W;
        const u32* SAl = SAh + LVL_W;
        const u32* SBh = SAh + 2 * LVL_W;
        const u32* SBl = SAh + 3 * LVL_W;

#pragma unroll
        for (int ks = 0; ks < 2; ks++) {
            int ko = ks * 8;
            u32 bh[4][2], bl[4][2];
#pragma unroll
            for (int nt = 0; nt < 4; nt++) {
                int rb = (wn + nt * 8 + g) * WROW + ko + t;
                bh[nt][0] = SBh[rb]; bh[nt][1] = SBh[rb + 4];
                bl[nt][0] = SBl[rb]; bl[nt][1] = SBl[rb + 4];
            }
#pragma unroll
            for (int mt = 0; mt < 4; mt++) {
                int r0 = (wm + mt * 16 + g) * WROW + ko + t;
                int r8 = r0 + 8 * WROW;
                u32 ah[4], al[4];
                ah[0] = SAh[r0]; ah[1] = SAh[r8];
                ah[2] = SAh[r0 + 4]; ah[3] = SAh[r8 + 4];
                al[0] = SAl[r0]; al[1] = SAl[r8];
                al[2] = SAl[r0 + 4]; al[3] = SAl[r8 + 4];
#pragma unroll
                for (int nt = 0; nt < 4; nt++) {
                    mma_f16(acc[mt][nt], ah, bh[nt]);   // hi*hi (exact in fp32)
                    mma_f16(acc[mt][nt], ah, bl[nt]);   // hi*lo
                    mma_f16(acc[mt][nt], al, bh[nt]);   // lo*hi
                }
            }
        }
        __syncthreads();
    }

#pragma unroll
    for (int mt = 0; mt < 4; mt++) {
#pragma unroll
        for (int nt = 0; nt < 4; nt++) {
            int r = m0 + wm + mt * 16 + g;
            int c = n0 + wn + nt * 8 + t * 2;
            if (c + 1 < N) {
                *(float2*)(C + (size_t)r * N + c) =
                    make_float2(acc[mt][nt][0], acc[mt][nt][1]);
                *(float2*)(C + (size_t)(r + 8) * N + c) =
                    make_float2(acc[mt][nt][2], acc[mt][nt][3]);
            } else if (c < N) {
                C[(size_t)r * N + c] = acc[mt][nt][0];
                C[(size_t)(r + 8) * N + c] = acc[mt][nt][2];
            }
        }
    }
}

// ---------------- K2: fused conv+silu+norms+expand -> xv, fv, rin, cg ----------------
__global__ __launch_bounds__(256) void convbuild_kernel(const float* __restrict__ conv_w,
                                                        const float* __restrict__ w_in_norm,
                                                        const float* __restrict__ w_f_norm,
                                                        const float* __restrict__ w_r_norm) {
    __shared__ float sy[CONVn];
    __shared__ float sb1[8], sb2[8];
    __shared__ float srs[1];
    int row = blockIdx.x;      // b*S + s
    int s = row % Sn;
    int tid = threadIdx.x;

    const float* p0 = g_proj + (size_t)row * NPROJ;
    for (int c = tid; c < CONVn; c += 256) {
        float w0 = conv_w[c * 4 + 0], w1 = conv_w[c * 4 + 1];
        float w2 = conv_w[c * 4 + 2], w3 = conv_w[c * 4 + 3];
        float acc = w3 * p0[c];
        if (s >= 1) acc += w2 * p0[c - NPROJ];
        if (s >= 2) acc += w1 * p0[c - 2 * NPROJ];
        if (s >= 3) acc += w0 * p0[c - 3 * NPROJ];
        sy[c] = acc * sigmoidf_(acc);
    }
    __syncthreads();

    float s1 = 0.f, s2 = 0.f;
    for (int i = tid; i < 512; i += 256) {
        s1 += sy[i] * sy[i];
        s2 += sy[512 + i] * sy[512 + i];
    }
    float t1 = blk_sum256(s1, sb1);
    float t2 = blk_sum256(s2, sb2);
    if (tid == 0) {
        float sr = 0.f;
#pragma unroll
        for (int h = 0; h < 8; h++) sr += sy[1024 + h] * sy[1024 + h];
        srs[0] = rsqrtf(sr * (1.f / 8.f) + 1e-6f);
    }
    float si = rsqrtf(t1 * (1.f / 512.f) + 1e-6f);
    float sf = rsqrtf(t2 * (1.f / 512.f) + 1e-6f);
    __syncthreads();

    float e0 = sy[1040], e1 = sy[1041];
    float* xv = g_xv + (size_t)row * 1024;
    float* fv = g_fv + (size_t)row * 1024;
#pragma unroll
    for (int q = 0; q < 4; q++) {
        int o = tid + q * 256;
        int hh = o >> 7, rem = o & 127, ee = rem >> 6, dd = rem & 63;
        int ii = hh * 64 + dd;
        float ex = (ee == 0) ? e0 : e1;
        xv[o] = sy[ii] * si * w_in_norm[ii] * ex;
        fv[o] = sy[512 + ii] * sf * w_f_norm[ii] * ex;
    }
    if (tid < 8) {
        g_rin[(size_t)row * 8 + tid] = sy[1024 + tid] * srs[0] * w_r_norm[tid];
        g_cg[(size_t)row * 8 + tid] = sy[1032 + tid];
    }
}

// ---------------- K3: sequential recurrence, one CTA per (b,h), 256 threads ----------------
// Pair-split: e = tid>>1, half = tid&1. Weights in registers (96 x 64-bit).
// Phase A: R-dot only. Phase B: F-dot + W-dot interleaved. h_sh double-buffered
// so phase-B reads of h never race the end-of-step h write.
__global__ __launch_bounds__(256, 1) void scan_kernel(const float* __restrict__ state_w,
                                                      const float* __restrict__ res_w) {
    int b = blockIdx.x >> 3, hh = blockIdx.x & 7;
    int tid = threadIdx.x;
    int e = tid >> 1, half = tid & 1;

    __shared__ __align__(16) float h_sh[2][128];
    __shared__ __align__(16) float rh_sh[128];
    __shared__ __align__(16) float xbuf[2][128];
    __shared__ __align__(16) float fbuf[2][128];
    __shared__ float rin_s[Sn], cg_s[Sn];
    __shared__ float sbuf[8];

    // --- fused state_w normalization + packed weight load ---
    const float* bw = state_w + (size_t)hh * 16384 + half * 64 * 128 + e;
    const float* bf = state_w + (size_t)(8 + hh) * 16384 + half * 64 * 128 + e;
    const float* br = state_w + (size_t)(16 + hh) * 16384 + half * 64 * 128 + e;
    float ssW = 0.f, ssF = 0.f, ssR = 0.f;
#pragma unroll 8
    for (int i = 0; i < 64; i++) {
        float vw = bw[i * 128], vf = bf[i * 128], vr = br[i * 128];
        ssW += vw * vw; ssF += vf * vf; ssR += vr * vr;
    }
    float totW = blk_sum256(ssW, sbuf);
    float totF = blk_sum256(ssF, sbuf);
    float totR = blk_sum256(ssR, sbuf);
    float invW = 1.f / fmaxf(sqrtf(totW), 1e-12f);
    float invF = 1.f / fmaxf(sqrtf(totF), 1e-12f);
    float invR = 1.f / fmaxf(sqrtf(totR), 1e-12f);

    ull W2[32], F2[32], R2[32];
#pragma unroll
    for (int i = 0; i < 32; i++) {
        W2[i] = pk2(bw[(2 * i) * 128] * invW, bw[(2 * i + 1) * 128] * invW);
        F2[i] = pk2(bf[(2 * i) * 128] * invF, bf[(2 * i + 1) * 128] * invF);
        R2[i] = pk2(br[(2 * i) * 128] * invR, br[(2 * i + 1) * 128] * invR);
    }

    for (int t = tid; t < Sn; t += 256) {
        rin_s[t] = g_rin[(size_t)(b * Sn + t) * 8 + hh];
        cg_s[t]  = g_cg[(size_t)(b * Sn + t) * 8 + hh];
    }
    if (tid < 128) h_sh[0][tid] = 0.f;
    float resw = res_w[hh];
    size_t rowbase = ((size_t)b * Sn) * 1024 + hh * 128;

    // prefetch t=0 (loader threads only)
    if (tid < 32)       cp_async16(&xbuf[0][tid * 4], g_xv + rowbase + tid * 4);
    else if (tid < 64)  cp_async16(&fbuf[0][(tid - 32) * 4], g_fv + rowbase + (tid - 32) * 4);
    if (tid < 64) asm volatile("cp.async.commit_group;");

    for (int t = 0; t < Sn; t++) {
        int cur = t & 1, nxt = cur ^ 1;
        __syncthreads();   // S1: h_sh[cur] (written at end of prev step) visible; nxt bufs free
        if (tid < 64) {
            if (t + 1 < Sn) {
                size_t nb = rowbase + (size_t)(t + 1) * 1024;
                if (tid < 32) cp_async16(&xbuf[nxt][tid * 4], g_xv + nb + tid * 4);
                else          cp_async16(&fbuf[nxt][(tid - 32) * 4], g_fv + nb + (tid - 32) * 4);
            }
            asm volatile("cp.async.commit_group;");
        }

        // ---- Phase A: R-dot only, dual accumulators (chain depth 8) ----
        const ulonglong2* h4 = (const ulonglong2*)(h_sh[cur]) + half * 8;
        ull pRa = 0ull, pRb = 0ull;
#pragma unroll
        for (int i = 0; i < 8; i++) {
            ulonglong2 hv = h4[i];
            pRa = ffma2(hv.x, R2[2 * i], pRa);
            pRb = ffma2(hv.y, R2[2 * i + 1], pRb);
        }
        float2 fa = u2f(pRa), fb = u2f(pRb);
        float pR = (fa.x + fa.y) + (fb.x + fb.y);
        pR += __shfl_xor_sync(0xffffffffu, pR, 1);

        float hcur_e = h_sh[cur][e];
        if (half == 0) {
            rh_sh[e] = sigmoidf_(rin_s[t] + pR) * hcur_e;
        }

        if (tid < 64) asm volatile("cp.async.wait_group 1;");
        __syncthreads();   // S2: rh_sh visible; xbuf/fbuf[cur] visible to all

        // ---- Phase B: F-dot (on h) + W-dot (on rh), interleaved ----
        const ulonglong2* rh4 = (const ulonglong2*)(rh_sh) + half * 8;
        ull pFa = 0ull, pFb = 0ull, pWa = 0ull, pWb = 0ull;
#pragma unroll
        for (int i = 0; i < 8; i++) {
            ulonglong2 hv = h4[i];
            ulonglong2 rv = rh4[i];
            pWa = ffma2(rv.x, W2[2 * i], pWa);
            pFa = ffma2(hv.x, F2[2 * i], pFa);
            pWb = ffma2(rv.y, W2[2 * i + 1], pWb);
            pFb = ffma2(hv.y, F2[2 * i + 1], pFb);
        }
        float2 wa = u2f(pWa), wb = u2f(pWb), ga = u2f(pFa), gb = u2f(pFb);
        float pW = (wa.x + wa.y) + (wb.x + wb.y);
        float pF = (ga.x + ga.y) + (gb.x + gb.y);
        pW += __shfl_xor_sync(0xffffffffu, pW, 1);
        pF += __shfl_xor_sync(0xffffffffu, pF, 1);

        float fgate = sigmoidf_(fbuf[cur][e] + pF);
        float xt = xbuf[cur][e];
        float htl = tanhf_(xt + pW);
        float hn = fgate * hcur_e + (1.f - fgate) * htl;
        if (half == 1) {
            h_sh[nxt][e] = hn;                                   // next step's h
        } else {
            g_scan[rowbase + (size_t)t * 1024 + e] = resw * xt + hn * cg_s[t];
        }
    }
}

// ---------------- K4: up-proj + gate silu + rms -> fp16 hi/lo v ----------------
__global__ __launch_bounds__(256) void ugate_kernel(const float* __restrict__ up_w,
                                                    const float* __restrict__ w_g_norm) {
    __shared__ float srow[1024];
    __shared__ float suw[64 * 129];
    __shared__ float sb[8];
    int row = blockIdx.x;
    int tid = threadIdx.x;

    const float* sr = g_scan + (size_t)row * 1024;
    for (int i = tid; i < 1024; i += 256) srow[i] = sr[i];
    for (int i = tid; i < 8192; i += 256) {
        int j = i >> 7, d = i & 127;
        suw[j * 129 + d] = up_w[i];
    }
    __syncthreads();

    int o0 = tid * 2, o1 = o0 + 1;
    int hhd = o0 >> 6;
    int j0 = o0 & 63, j1 = o1 & 63;
    const float* a = srow + hhd * 128;
    float acc0 = 0.f, acc1 = 0.f;
#pragma unroll 16
    for (int d = 0; d < 128; d++) {
        float av = a[d];
        acc0 += av * suw[j0 * 129 + d];
        acc1 += av * suw[j1 * 129 + d];
    }
    const float* gptr = g_proj + (size_t)row * NPROJ + CONVn;
    float gA = gptr[o0], gB = gptr[o1];
    float u0 = acc0 * (gA * sigmoidf_(gA));
    float u1 = acc1 * (gB * sigmoidf_(gB));

    float tot = blk_sum256(u0 * u0 + u1 * u1, sb);
    float scale = rsqrtf(tot * (1.f / 512.f) + 1e-6f);
    float v0 = u0 * scale * w_g_norm[o0];
    float v1 = u1 * scale * w_g_norm[o1];

    size_t ob = (size_t)row * 512;
    __half h0 = __float2half_rn(v0), h1 = __float2half_rn(v1);
    g_vh[ob + o0] = h0;
    g_vh[ob + o1] = h1;
    g_vl[ob + o0] = __float2half_rn(v0 - __half2float(h0));
    g_vl[ob + o1] = __float2half_rn(v1 - __half2float(h1));
}

// ---------------- launch ----------------
extern "C" void kernel_launch(void* const* d_in, const int* in_sizes, int n_in,
                              void* d_out, int out_size) {
    const float* x         = (const float*)d_in[0];
    const float* w_in      = (const float*)d_in[1];
    const float* conv_w    = (const float*)d_in[2];
    const float* state_w   = (const float*)d_in[3];
    const float* up_w      = (const float*)d_in[4];
    const float* out_w     = (const float*)d_in[5];
    const float* res_w     = (const float*)d_in[6];
    const float* w_in_norm = (const float*)d_in[7];
    const float* w_f_norm  = (const float*)d_in[8];
    const float* w_r_norm  = (const float*)d_in[9];
    const float* w_g_norm  = (const float*)d_in[10];
    float* out = (float*)d_out;

    float* p_proj = nullptr;
    cudaGetSymbolAddress((void**)&p_proj, g_proj);
    __half *p_xh, *p_xl, *p_wh, *p_wl, *p_owh, *p_owl, *p_vh, *p_vl;
    cudaGetSymbolAddress((void**)&p_xh, g_xh);
    cudaGetSymbolAddress((void**)&p_xl, g_xl);
    cudaGetSymbolAddress((void**)&p_wh, g_wh);
    cudaGetSymbolAddress((void**)&p_wl, g_wl);
    cudaGetSymbolAddress((void**)&p_owh, g_owh);
    cudaGetSymbolAddress((void**)&p_owl, g_owl);
    cudaGetSymbolAddress((void**)&p_vh, g_vh);
    cudaGetSymbolAddress((void**)&p_vl, g_vl);

    cudaFuncSetAttribute(h2s_gemm_nt, cudaFuncAttributeMaxDynamicSharedMemorySize,
                         TC_SMEM_DYN);

    // #1: all operand splits
    cvt_all_kernel<<<(NX + NW + NO + 255) / 256, 256>>>(x, w_in, out_w);
    // #2: proj = x @ w_in^T
    h2s_gemm_nt<<<dim3(NPPAD / TCN, BSn / TCM), 256, TC_SMEM_DYN>>>(
        p_xh, p_xl, p_wh, p_wl, p_proj, BSn, NPROJ, Dn);
    // #3: fused conv+silu+norms+expand
    convbuild_kernel<<<BSn, 256>>>(conv_w, w_in_norm, w_f_norm, w_r_norm);
    // #4: sequential scan (profiled by ncu)
    scan_kernel<<<Bn * Hn, 256>>>(state_w, res_w);
    // #5: up-proj + gate + rms
    ugate_kernel<<<BSn, 256>>>(up_w, w_g_norm);
    // #6: final = v @ out_w^T
    h2s_gemm_nt<<<dim3(Dn / TCN, BSn / TCM), 256, TC_SMEM_DYN>>>(
        p_vh, p_vl, p_owh, p_owl, out, BSn, Dn, LRn);
}

// round 13
// speedup vs baseline: 2.7890x; 1.0039x over previous
#include <cuda_runtime.h>
#include <cuda_fp16.h>
#include <math.h>

#define Bn    4
#define Sn    2048
#define Dn    1024
#define Hn    8
#define LRn   512
#define LRHn  64
#define SHDn  128
#define EXPn  2
#define Kn    4
#define CONVn 1042
#define NPROJ 1554
#define NPPAD 1664   // NPROJ padded to multiple of 128
#define BSn   8192   // B*S

typedef unsigned long long ull;
typedef unsigned int u32;

// ---------------- scratch (device globals; no runtime allocation) ----------------
__device__ float g_proj[BSn * NPROJ];
__device__ float g_xv[BSn * 1024];
__device__ float g_fv[BSn * 1024];
__device__ float g_scan[BSn * 1024];
__device__ float g_rin[BSn * Hn];
__device__ float g_cg[BSn * Hn];
// fp16 hi/lo operand splits
__device__ __align__(16) __half g_xh[BSn * Dn];
__device__ __align__(16) __half g_xl[BSn * Dn];
__device__ __align__(16) __half g_wh[NPPAD * Dn];
__device__ __align__(16) __half g_wl[NPPAD * Dn];
__device__ __align__(16) __half g_owh[Dn * LRn];
__device__ __align__(16) __half g_owl[Dn * LRn];
__device__ __align__(16) __half g_vh[BSn * LRn];
__device__ __align__(16) __half g_vl[BSn * LRn];

// ---------------- helpers ----------------
__device__ __forceinline__ float sigmoidf_(float x) {
    return __fdividef(1.f, 1.f + __expf(-x));
}
__device__ __forceinline__ float tanhf_(float x) {
    float t = __expf(-2.f * fabsf(x));
    float r = __fdividef(1.f - t, 1.f + t);
    return copysignf(r, x);
}
__device__ __forceinline__ float blk_sum256(float v, float* sbuf) {
    int lane = threadIdx.x & 31, wid = threadIdx.x >> 5;
#pragma unroll
    for (int off = 16; off; off >>= 1) v += __shfl_xor_sync(0xffffffffu, v, off);
    if (lane == 0) sbuf[wid] = v;
    __syncthreads();
    float tot = 0.f;
#pragma unroll
    for (int i = 0; i < 8; i++) tot += sbuf[i];
    __syncthreads();
    return tot;
}
__device__ __forceinline__ void cp_async16_s(u32 saddr, const void* gmem) {
    asm volatile("cp.async.cg.shared.global [%0], [%1], 16;\n" ::"r"(saddr), "l"(gmem));
}

// ---- packed fp32x2 ----
__device__ __forceinline__ ull ffma2(ull a, ull b, ull c) {
    ull d;
    asm("fma.rn.f32x2 %0, %1, %2, %3;" : "=l"(d) : "l"(a), "l"(b), "l"(c));
    return d;
}
__device__ __forceinline__ ull pk2(float x, float y) {
    ull r;
    asm("mov.b64 %0, {%1, %2};" : "=l"(r) : "f"(x), "f"(y));
    return r;
}
__device__ __forceinline__ float2 u2f(ull v) {
    float2 f;
    asm("mov.b64 {%0, %1}, %2;" : "=f"(f.x), "=f"(f.y) : "l"(v));
    return f;
}

// ---- fp16 mma m16n8k16 ----
__device__ __forceinline__ void mma_f16(float* d, const u32* a, const u32* b) {
    asm volatile(
        "mma.sync.aligned.m16n8k16.row.col.f32.f16.f16.f32 "
        "{%0,%1,%2,%3}, {%4,%5,%6,%7}, {%8,%9}, {%0,%1,%2,%3};"
        : "+f"(d[0]), "+f"(d[1]), "+f"(d[2]), "+f"(d[3])
        : "r"(a[0]), "r"(a[1]), "r"(a[2]), "r"(a[3]), "r"(b[0]), "r"(b[1]));
}

// ---------------- K0: all f32 -> fp16 hi/lo splits in one launch ----------------
#define NX (BSn * Dn)
#define NW (NPPAD * Dn)
#define NO (Dn * LRn)
__global__ __launch_bounds__(256) void cvt_all_kernel(const float* __restrict__ x,
                                                      const float* __restrict__ w_in,
                                                      const float* __restrict__ out_w) {
    int i = blockIdx.x * 256 + threadIdx.x;
    if (i < NX) {
        float v = x[i];
        __half h = __float2half_rn(v);
        g_xh[i] = h;
        g_xl[i] = __float2half_rn(v - __half2float(h));
        return;
    }
    int j = i - NX;
    if (j < NW) {
        float v = (j < NPROJ * Dn) ? w_in[j] : 0.f;
        __half h = __float2half_rn(v);
        g_wh[j] = h;
        g_wl[j] = __float2half_rn(v - __half2float(h));
        return;
    }
    int k2 = j - NW;
    if (k2 < NO) {
        float v = out_w[k2];
        __half h = __float2half_rn(v);
        g_owh[k2] = h;
        g_owl[k2] = __float2half_rn(v - __half2float(h));
    }
}

// ---------------- fp16-split tensor-core GEMM: C[M,N] = A @ B^T ----------------
#define TCM 128
#define TCN 128
#define TCKC 32
#define WROW 20
#define LVL_W (128 * WROW)
#define BUF_W (4 * LVL_W)
#define TC_SMEM_DYN (2 * BUF_W * 4) // 81920 bytes

__global__ __launch_bounds__(256) void h2s_gemm_nt(const __half* __restrict__ Ah,
                                                   const __half* __restrict__ Al,
                                                   const __half* __restrict__ Bh,
                                                   const __half* __restrict__ Bl,
                                                   float* __restrict__ C,
                                                   int M, int N, int Kd) {
    extern __shared__ u32 sm[];
    int tid = threadIdx.x;
    int wid = tid >> 5, lane = tid & 31;
    int g = lane >> 2, t = lane & 3;
    int wm = (wid >> 2) * 64, wn = (wid & 3) * 32;
    int m0 = blockIdx.y * TCM, n0 = blockIdx.x * TCN;

    u32 sbase = (u32)__cvta_generic_to_shared(sm);

    const __half* srcA_h = Ah + (size_t)m0 * Kd;
    const __half* srcA_l = Al + (size_t)m0 * Kd;
    const __half* srcB_h = Bh + (size_t)n0 * Kd;
    const __half* srcB_l = Bl + (size_t)n0 * Kd;

    float acc[4][4][4];
#pragma unroll
    for (int i = 0; i < 4; i++)
#pragma unroll
        for (int j = 0; j < 4; j++)
#pragma unroll
            for (int q = 0; q < 4; q++) acc[i][j][q] = 0.f;

    int row2 = tid >> 2, j4 = tid & 3;
    const int nchunks = Kd / TCKC;

#define ISSUE_CHUNK(ck, buf) do {                                              \
        int k0_ = (ck) * TCKC;                                                 \
        u32 b_ = sbase + (buf) * BUF_W * 4;                                    \
        const __half* s0;                                                      \
        s0 = srcA_h + (size_t)row2 * Kd + k0_ + j4 * 8;                        \
        cp_async16_s(b_ + (0 * LVL_W + row2 * WROW + j4 * 4) * 4, s0);         \
        cp_async16_s(b_ + (0 * LVL_W + (row2 + 64) * WROW + j4 * 4) * 4,       \
                     s0 + (size_t)64 * Kd);                                    \
        s0 = srcA_l + (size_t)row2 * Kd + k0_ + j4 * 8;                        \
        cp_async16_s(b_ + (1 * LVL_W + row2 * WROW + j4 * 4) * 4, s0);         \
        cp_async16_s(b_ + (1 * LVL_W + (row2 + 64) * WROW + j4 * 4) * 4,       \
                     s0 + (size_t)64 * Kd);                                    \
        s0 = srcB_h + (size_t)row2 * Kd + k0_ + j4 * 8;                        \
        cp_async16_s(b_ + (2 * LVL_W + row2 * WROW + j4 * 4) * 4, s0);         \
        cp_async16_s(b_ + (2 * LVL_W + (row2 + 64) * WROW + j4 * 4) * 4,       \
                     s0 + (size_t)64 * Kd);                                    \
        s0 = srcB_l + (size_t)row2 * Kd + k0_ + j4 * 8;                        \
        cp_async16_s(b_ + (3 * LVL_W + row2 * WROW + j4 * 4) * 4, s0);         \
        cp_async16_s(b_ + (3 * LVL_W + (row2 + 64) * WROW + j4 * 4) * 4,       \
                     s0 + (size_t)64 * Kd);                                    \
        asm volatile("cp.async.commit_group;");                                \
    } while (0)

    ISSUE_CHUNK(0, 0);

    for (int ck = 0; ck < nchunks; ck++) {
        int cur = ck & 1;
        bool has_next = (ck + 1 < nchunks);
        if (has_next) {
            ISSUE_CHUNK(ck + 1, cur ^ 1);
            asm volatile("cp.async.wait_group 1;");
        } else {
            asm volatile("cp.async.wait_group 0;");
        }
        __syncthreads();

        const u32* SAh = sm + cur * BUF_W;
        const u32* SAl = SAh + LVL_W;
        const u32* SBh = SAh + 2 * LVL_W;
        const u32* SBl = SAh + 3 * LVL_W;

#pragma unroll
        for (int ks = 0; ks < 2; ks++) {
            int ko = ks * 8;
            u32 bh[4][2], bl[4][2];
#pragma unroll
            for (int nt = 0; nt < 4; nt++) {
                int rb = (wn + nt * 8 + g) * WROW + ko + t;
                bh[nt][0] = SBh[rb]; bh[nt][1] = SBh[rb + 4];
                bl[nt][0] = SBl[rb]; bl[nt][1] = SBl[rb + 4];
            }
#pragma unroll
            for (int mt = 0; mt < 4; mt++) {
                int r0 = (wm + mt * 16 + g) * WROW + ko + t;
                int r8 = r0 + 8 * WROW;
                u32 ah[4], al[4];
                ah[0] = SAh[r0]; ah[1] = SAh[r8];
                ah[2] = SAh[r0 + 4]; ah[3] = SAh[r8 + 4];
                al[0] = SAl[r0]; al[1] = SAl[r8];
                al[2] = SAl[r0 + 4]; al[3] = SAl[r8 + 4];
#pragma unroll
                for (int nt = 0; nt < 4; nt++) {
                    mma_f16(acc[mt][nt], ah, bh[nt]);   // hi*hi (exact in fp32)
                    mma_f16(acc[mt][nt], ah, bl[nt]);   // hi*lo
                    mma_f16(acc[mt][nt], al, bh[nt]);   // lo*hi
                }
            }
        }
        __syncthreads();
    }

#pragma unroll
    for (int mt = 0; mt < 4; mt++) {
#pragma unroll
        for (int nt = 0; nt < 4; nt++) {
            int r = m0 + wm + mt * 16 + g;
            int c = n0 + wn + nt * 8 + t * 2;
            if (c + 1 < N) {
                *(float2*)(C + (size_t)r * N + c) =
                    make_float2(acc[mt][nt][0], acc[mt][nt][1]);
                *(float2*)(C + (size_t)(r + 8) * N + c) =
                    make_float2(acc[mt][nt][2], acc[mt][nt][3]);
            } else if (c < N) {
                C[(size_t)r * N + c] = acc[mt][nt][0];
                C[(size_t)(r + 8) * N + c] = acc[mt][nt][2];
            }
        }
    }
}

// ---------------- K2: fused conv+silu+norms+expand -> xv, fv, rin, cg ----------------
__global__ __launch_bounds__(256) void convbuild_kernel(const float* __restrict__ conv_w,
                                                        const float* __restrict__ w_in_norm,
                                                        const float* __restrict__ w_f_norm,
                                                        const float* __restrict__ w_r_norm) {
    __shared__ float sy[CONVn];
    __shared__ float sb1[8], sb2[8];
    __shared__ float srs[1];
    int row = blockIdx.x;      // b*S + s
    int s = row % Sn;
    int tid = threadIdx.x;

    const float* p0 = g_proj + (size_t)row * NPROJ;
    for (int c = tid; c < CONVn; c += 256) {
        float w0 = conv_w[c * 4 + 0], w1 = conv_w[c * 4 + 1];
        float w2 = conv_w[c * 4 + 2], w3 = conv_w[c * 4 + 3];
        float acc = w3 * p0[c];
        if (s >= 1) acc += w2 * p0[c - NPROJ];
        if (s >= 2) acc += w1 * p0[c - 2 * NPROJ];
        if (s >= 3) acc += w0 * p0[c - 3 * NPROJ];
        sy[c] = acc * sigmoidf_(acc);
    }
    __syncthreads();

    float s1 = 0.f, s2 = 0.f;
    for (int i = tid; i < 512; i += 256) {
        s1 += sy[i] * sy[i];
        s2 += sy[512 + i] * sy[512 + i];
    }
    float t1 = blk_sum256(s1, sb1);
    float t2 = blk_sum256(s2, sb2);
    if (tid == 0) {
        float sr = 0.f;
#pragma unroll
        for (int h = 0; h < 8; h++) sr += sy[1024 + h] * sy[1024 + h];
        srs[0] = rsqrtf(sr * (1.f / 8.f) + 1e-6f);
    }
    float si = rsqrtf(t1 * (1.f / 512.f) + 1e-6f);
    float sf = rsqrtf(t2 * (1.f / 512.f) + 1e-6f);
    __syncthreads();

    float e0 = sy[1040], e1 = sy[1041];
    float* xv = g_xv + (size_t)row * 1024;
    float* fv = g_fv + (size_t)row * 1024;
#pragma unroll
    for (int q = 0; q < 4; q++) {
        int o = tid + q * 256;
        int hh = o >> 7, rem = o & 127, ee = rem >> 6, dd = rem & 63;
        int ii = hh * 64 + dd;
        float ex = (ee == 0) ? e0 : e1;
        xv[o] = sy[ii] * si * w_in_norm[ii] * ex;
        fv[o] = sy[512 + ii] * sf * w_f_norm[ii] * ex;
    }
    if (tid < 8) {
        g_rin[(size_t)row * 8 + tid] = sy[1024 + tid] * srs[0] * w_r_norm[tid];
        g_cg[(size_t)row * 8 + tid] = sy[1032 + tid];
    }
}

// ---------------- K3: sequential recurrence, one CTA per (b,h), 256 threads ----------------
// Pair-split: e = tid>>1, half = tid&1. Weights in registers.
// Per-thread register LDG queue (depth 8) replaces cp.async smem buffers.
// half==1 computes gate/tanh/h-update; half==0 receives hn via shfl and stores.
__global__ __launch_bounds__(256, 1) void scan_kernel(const float* __restrict__ state_w,
                                                      const float* __restrict__ res_w) {
    int b = blockIdx.x >> 3, hh = blockIdx.x & 7;
    int tid = threadIdx.x;
    int e = tid >> 1, half = tid & 1;

    __shared__ __align__(16) float h_sh[2][128];
    __shared__ __align__(16) float rh_sh[128];
    __shared__ float rin_s[Sn], cg_s[Sn];
    __shared__ float sbuf[8];

    // --- fused state_w normalization + packed weight load ---
    const float* bw = state_w + (size_t)hh * 16384 + half * 64 * 128 + e;
    const float* bf = state_w + (size_t)(8 + hh) * 16384 + half * 64 * 128 + e;
    const float* br = state_w + (size_t)(16 + hh) * 16384 + half * 64 * 128 + e;
    float ssW = 0.f, ssF = 0.f, ssR = 0.f;
#pragma unroll 8
    for (int i = 0; i < 64; i++) {
        float vw = bw[i * 128], vf = bf[i * 128], vr = br[i * 128];
        ssW += vw * vw; ssF += vf * vf; ssR += vr * vr;
    }
    float totW = blk_sum256(ssW, sbuf);
    float totF = blk_sum256(ssF, sbuf);
    float totR = blk_sum256(ssR, sbuf);
    float invW = 1.f / fmaxf(sqrtf(totW), 1e-12f);
    float invF = 1.f / fmaxf(sqrtf(totF), 1e-12f);
    float invR = 1.f / fmaxf(sqrtf(totR), 1e-12f);

    ull W2[32], F2[32], R2[32];
#pragma unroll
    for (int i = 0; i < 32; i++) {
        W2[i] = pk2(bw[(2 * i) * 128] * invW, bw[(2 * i + 1) * 128] * invW);
        F2[i] = pk2(bf[(2 * i) * 128] * invF, bf[(2 * i + 1) * 128] * invF);
        R2[i] = pk2(br[(2 * i) * 128] * invR, br[(2 * i + 1) * 128] * invR);
    }

    for (int t = tid; t < Sn; t += 256) {
        rin_s[t] = g_rin[(size_t)(b * Sn + t) * 8 + hh];
        cg_s[t]  = g_cg[(size_t)(b * Sn + t) * 8 + hh];
    }
    if (tid < 128) h_sh[0][tid] = 0.f;
    float resw = res_w[hh];
    size_t rowbase = ((size_t)b * Sn) * 1024 + hh * 128;
    const float* xsrc = g_xv + rowbase + e;   // stride 1024 per step
    const float* fsrc = g_fv + rowbase + e;

    // prefill LDG queue (t = 0..7)
    float xq[8], fq[8];
#pragma unroll
    for (int s = 0; s < 8; s++) {
        xq[s] = xsrc[(size_t)s * 1024];
        fq[s] = fsrc[(size_t)s * 1024];
    }

    for (int t8 = 0; t8 < Sn / 8; t8++) {
#pragma unroll
        for (int s = 0; s < 8; s++) {
            int t = t8 * 8 + s;
            int cur = t & 1, nxt = cur ^ 1;
            __syncthreads();   // S1: h_sh[cur] visible

            // ---- Phase A: R-dot (dual accumulators, chain depth 8) ----
            const ulonglong2* h4 = (const ulonglong2*)(h_sh[cur]) + half * 8;
            ull pRa = 0ull, pRb = 0ull;
#pragma unroll
            for (int i = 0; i < 8; i++) {
                ulonglong2 hv = h4[i];
                pRa = ffma2(hv.x, R2[2 * i], pRa);
                pRb = ffma2(hv.y, R2[2 * i + 1], pRb);
            }
            float2 fa = u2f(pRa), fb = u2f(pRb);
            float pR = (fa.x + fa.y) + (fb.x + fb.y);
            pR += __shfl_xor_sync(0xffffffffu, pR, 1);

            float hcur_e = h_sh[cur][e];
            if (half == 0) {
                rh_sh[e] = sigmoidf_(rin_s[t] + pR) * hcur_e;
            }
            __syncthreads();   // S2: rh_sh visible

            // consume queue slot s; refill with t+8
            float xt = xq[s], ft = fq[s];
            {
                int tp = t + 8;
                if (tp < Sn) {
                    xq[s] = xsrc[(size_t)tp * 1024];
                    fq[s] = fsrc[(size_t)tp * 1024];
                }
            }

            // ---- Phase B: F-dot (on h) + W-dot (on rh), interleaved ----
            const ulonglong2* rh4 = (const ulonglong2*)(rh_sh) + half * 8;
            ull pFa = 0ull, pFb = 0ull, pWa = 0ull, pWb = 0ull;
#pragma unroll
            for (int i = 0; i < 8; i++) {
                ulonglong2 hv = h4[i];
                ulonglong2 rv = rh4[i];
                pWa = ffma2(rv.x, W2[2 * i], pWa);
                pFa = ffma2(hv.x, F2[2 * i], pFa);
                pWb = ffma2(rv.y, W2[2 * i + 1], pWb);
                pFb = ffma2(hv.y, F2[2 * i + 1], pFb);
            }
            float2 wa = u2f(pWa), wb = u2f(pWb), ga = u2f(pFa), gb = u2f(pFb);
            float pW = (wa.x + wa.y) + (wb.x + wb.y);
            float pF = (ga.x + ga.y) + (gb.x + gb.y);
            pW += __shfl_xor_sync(0xffffffffu, pW, 1);
            pF += __shfl_xor_sync(0xffffffffu, pF, 1);

            float hn = 0.f;
            if (half == 1) {
                float fgate = sigmoidf_(ft + pF);
                float htl = tanhf_(xt + pW);
                hn = fgate * hcur_e + (1.f - fgate) * htl;
                h_sh[nxt][e] = hn;                         // next step's h
            }
            float hn_b = __shfl_xor_sync(0xffffffffu, hn, 1);
            if (half == 0) {
                g_scan[rowbase + (size_t)t * 1024 + e] = resw * xt + hn_b * cg_s[t];
            }
        }
    }
}

// ---------------- K4: up-proj + gate silu + rms -> fp16 hi/lo v ----------------
__global__ __launch_bounds__(256) void ugate_kernel(const float* __restrict__ up_w,
                                                    const float* __restrict__ w_g_norm) {
    __shared__ float srow[1024];
    __shared__ float suw[64 * 129];
    __shared__ float sb[8];
    int row = blockIdx.x;
    int tid = threadIdx.x;

    const float* sr = g_scan + (size_t)row * 1024;
    for (int i = tid; i < 1024; i += 256) srow[i] = sr[i];
    for (int i = tid; i < 8192; i += 256) {
        int j = i >> 7, d = i & 127;
        suw[j * 129 + d] = up_w[i];
    }
    __syncthreads();

    int o0 = tid * 2, o1 = o0 + 1;
    int hhd = o0 >> 6;
    int j0 = o0 & 63, j1 = o1 & 63;
    const float* a = srow + hhd * 128;
    float acc0 = 0.f, acc1 = 0.f;
#pragma unroll 16
    for (int d = 0; d < 128; d++) {
        float av = a[d];
        acc0 += av * suw[j0 * 129 + d];
        acc1 += av * suw[j1 * 129 + d];
    }
    const float* gptr = g_proj + (size_t)row * NPROJ + CONVn;
    float gA = gptr[o0], gB = gptr[o1];
    float u0 = acc0 * (gA * sigmoidf_(gA));
    float u1 = acc1 * (gB * sigmoidf_(gB));

    float tot = blk_sum256(u0 * u0 + u1 * u1, sb);
    float scale = rsqrtf(tot * (1.f / 512.f) + 1e-6f);
    float v0 = u0 * scale * w_g_norm[o0];
    float v1 = u1 * scale * w_g_norm[o1];

    size_t ob = (size_t)row * 512;
    __half h0 = __float2half_rn(v0), h1 = __float2half_rn(v1);
    g_vh[ob + o0] = h0;
    g_vh[ob + o1] = h1;
    g_vl[ob + o0] = __float2half_rn(v0 - __half2float(h0));
    g_vl[ob + o1] = __float2half_rn(v1 - __half2float(h1));
}

// ---------------- launch ----------------
extern "C" void kernel_launch(void* const* d_in, const int* in_sizes, int n_in,
                              void* d_out, int out_size) {
    const float* x         = (const float*)d_in[0];
    const float* w_in      = (const float*)d_in[1];
    const float* conv_w    = (const float*)d_in[2];
    const float* state_w   = (const float*)d_in[3];
    const float* up_w      = (const float*)d_in[4];
    const float* out_w     = (const float*)d_in[5];
    const float* res_w     = (const float*)d_in[6];
    const float* w_in_norm = (const float*)d_in[7];
    const float* w_f_norm  = (const float*)d_in[8];
    const float* w_r_norm  = (const float*)d_in[9];
    const float* w_g_norm  = (const float*)d_in[10];
    float* out = (float*)d_out;

    float* p_proj = nullptr;
    cudaGetSymbolAddress((void**)&p_proj, g_proj);
    __half *p_xh, *p_xl, *p_wh, *p_wl, *p_owh, *p_owl, *p_vh, *p_vl;
    cudaGetSymbolAddress((void**)&p_xh, g_xh);
    cudaGetSymbolAddress((void**)&p_xl, g_xl);
    cudaGetSymbolAddress((void**)&p_wh, g_wh);
    cudaGetSymbolAddress((void**)&p_wl, g_wl);
    cudaGetSymbolAddress((void**)&p_owh, g_owh);
    cudaGetSymbolAddress((void**)&p_owl, g_owl);
    cudaGetSymbolAddress((void**)&p_vh, g_vh);
    cudaGetSymbolAddress((void**)&p_vl, g_vl);

    cudaFuncSetAttribute(h2s_gemm_nt, cudaFuncAttributeMaxDynamicSharedMemorySize,
                         TC_SMEM_DYN);

    // #1: all operand splits
    cvt_all_kernel<<<(NX + NW + NO + 255) / 256, 256>>>(x, w_in, out_w);
    // #2: proj = x @ w_in^T
    h2s_gemm_nt<<<dim3(NPPAD / TCN, BSn / TCM), 256, TC_SMEM_DYN>>>(
        p_xh, p_xl, p_wh, p_wl, p_proj, BSn, NPROJ, Dn);
    // #3: fused conv+silu+norms+expand
    convbuild_kernel<<<BSn, 256>>>(conv_w, w_in_norm, w_f_norm, w_r_norm);
    // #4: sequential scan (profiled by ncu)
    scan_kernel<<<Bn * Hn, 256>>>(state_w, res_w);
    // #5: up-proj + gate + rms
    ugate_kernel<<<BSn, 256>>>(up_w, w_g_norm);
    // #6: final = v @ out_w^T
    h2s_gemm_nt<<<dim3(Dn / TCN, BSn / TCM), 256, TC_SMEM_DYN>>>(
        p_vh, p_vl, p_owh, p_owl, out, BSn, Dn, LRn);
}

// round 15
// speedup vs baseline: 3.0622x; 1.0980x over previous
#include <cuda_runtime.h>
#include <cuda_fp16.h>
#include <math.h>

#define Bn    4
#define Sn    2048
#define Dn    1024
#define Hn    8
#define LRn   512
#define LRHn  64
#define SHDn  128
#define EXPn  2
#define Kn    4
#define CONVn 1042
#define NPROJ 1554
#define NPPAD 1664   // NPROJ padded to multiple of 128
#define BSn   8192   // B*S

typedef unsigned long long ull;
typedef unsigned int u32;

// ---------------- scratch (device globals; no runtime allocation) ----------------
__device__ float g_proj[BSn * NPROJ];
__device__ float g_xv[BSn * 1024];
__device__ float g_fv[BSn * 1024];
__device__ float g_scan[BSn * 1024];
__device__ float g_rin[BSn * Hn];
__device__ float g_cg[BSn * Hn];
__device__ int   g_prog[Bn];            // scan progress: 8 arrivals per 64-step block per batch
// fp16 hi/lo operand splits
__device__ __align__(16) __half g_xh[BSn * Dn];
__device__ __align__(16) __half g_xl[BSn * Dn];
__device__ __align__(16) __half g_wh[NPPAD * Dn];
__device__ __align__(16) __half g_wl[NPPAD * Dn];
__device__ __align__(16) __half g_owh[Dn * LRn];
__device__ __align__(16) __half g_owl[Dn * LRn];
__device__ __align__(16) __half g_vh[BSn * LRn];
__device__ __align__(16) __half g_vl[BSn * LRn];

// ---------------- helpers ----------------
__device__ __forceinline__ float sigmoidf_(float x) {
    return __fdividef(1.f, 1.f + __expf(-x));
}
__device__ __forceinline__ float tanhf_(float x) {
    float t = __expf(-2.f * fabsf(x));
    float r = __fdividef(1.f - t, 1.f + t);
    return copysignf(r, x);
}
__device__ __forceinline__ float blk_sum256(float v, float* sbuf) {
    int lane = threadIdx.x & 31, wid = threadIdx.x >> 5;
#pragma unroll
    for (int off = 16; off; off >>= 1) v += __shfl_xor_sync(0xffffffffu, v, off);
    if (lane == 0) sbuf[wid] = v;
    __syncthreads();
    float tot = 0.f;
#pragma unroll
    for (int i = 0; i < 8; i++) tot += sbuf[i];
    __syncthreads();
    return tot;
}
__device__ __forceinline__ void cp_async16_s(u32 saddr, const void* gmem) {
    asm volatile("cp.async.cg.shared.global [%0], [%1], 16;\n" ::"r"(saddr), "l"(gmem));
}

// ---- packed fp32x2 ----
__device__ __forceinline__ ull ffma2(ull a, ull b, ull c) {
    ull d;
    asm("fma.rn.f32x2 %0, %1, %2, %3;" : "=l"(d) : "l"(a), "l"(b), "l"(c));
    return d;
}
__device__ __forceinline__ ull pk2(float x, float y) {
    ull r;
    asm("mov.b64 %0, {%1, %2};" : "=l"(r) : "f"(x), "f"(y));
    return r;
}
__device__ __forceinline__ float2 u2f(ull v) {
    float2 f;
    asm("mov.b64 {%0, %1}, %2;" : "=f"(f.x), "=f"(f.y) : "l"(v));
    return f;
}

// ---- fp16 mma m16n8k16 ----
__device__ __forceinline__ void mma_f16(float* d, const u32* a, const u32* b) {
    asm volatile(
        "mma.sync.aligned.m16n8k16.row.col.f32.f16.f16.f32 "
        "{%0,%1,%2,%3}, {%4,%5,%6,%7}, {%8,%9}, {%0,%1,%2,%3};"
        : "+f"(d[0]), "+f"(d[1]), "+f"(d[2]), "+f"(d[3])
        : "r"(a[0]), "r"(a[1]), "r"(a[2]), "r"(a[3]), "r"(b[0]), "r"(b[1]));
}

// ---------------- K0: all f32 -> fp16 hi/lo splits in one launch ----------------
#define NX (BSn * Dn)
#define NW (NPPAD * Dn)
#define NO (Dn * LRn)
__global__ __launch_bounds__(256) void cvt_all_kernel(const float* __restrict__ x,
                                                      const float* __restrict__ w_in,
                                                      const float* __restrict__ out_w) {
    int i = blockIdx.x * 256 + threadIdx.x;
    if (i < Bn) g_prog[i] = 0;          // reset progress counters each invocation
    if (i < NX) {
        float v = x[i];
        __half h = __float2half_rn(v);
        g_xh[i] = h;
        g_xl[i] = __float2half_rn(v - __half2float(h));
        return;
    }
    int j = i - NX;
    if (j < NW) {
        float v = (j < NPROJ * Dn) ? w_in[j] : 0.f;
        __half h = __float2half_rn(v);
        g_wh[j] = h;
        g_wl[j] = __float2half_rn(v - __half2float(h));
        return;
    }
    int k2 = j - NW;
    if (k2 < NO) {
        float v = out_w[k2];
        __half h = __float2half_rn(v);
        g_owh[k2] = h;
        g_owl[k2] = __float2half_rn(v - __half2float(h));
    }
}

// ---------------- fp16-split tensor-core GEMM: C[M,N] = A @ B^T ----------------
#define TCM 128
#define TCN 128
#define TCKC 32
#define WROW 20
#define LVL_W (128 * WROW)
#define BUF_W (4 * LVL_W)
#define TC_SMEM_DYN (2 * BUF_W * 4) // 81920 bytes

__global__ __launch_bounds__(256) void h2s_gemm_nt(const __half* __restrict__ Ah,
                                                   const __half* __restrict__ Al,
                                                   const __half* __restrict__ Bh,
                                                   const __half* __restrict__ Bl,
                                                   float* __restrict__ C,
                                                   int M, int N, int Kd) {
    extern __shared__ u32 sm[];
    int tid = threadIdx.x;
    int wid = tid >> 5, lane = tid & 31;
    int g = lane >> 2, t = lane & 3;
    int wm = (wid >> 2) * 64, wn = (wid & 3) * 32;
    int m0 = blockIdx.y * TCM, n0 = blockIdx.x * TCN;

    u32 sbase = (u32)__cvta_generic_to_shared(sm);

    const __half* srcA_h = Ah + (size_t)m0 * Kd;
    const __half* srcA_l = Al + (size_t)m0 * Kd;
    const __half* srcB_h = Bh + (size_t)n0 * Kd;
    const __half* srcB_l = Bl + (size_t)n0 * Kd;

    float acc[4][4][4];
#pragma unroll
    for (int i = 0; i < 4; i++)
#pragma unroll
        for (int j = 0; j < 4; j++)
#pragma unroll
            for (int q = 0; q < 4; q++) acc[i][j][q] = 0.f;

    int row2 = tid >> 2, j4 = tid & 3;
    const int nchunks = Kd / TCKC;

#define ISSUE_CHUNK(ck, buf) do {                                              \
        int k0_ = (ck) * TCKC;                                                 \
        u32 b_ = sbase + (buf) * BUF_W * 4;                                    \
        const __half* s0;                                                      \
        s0 = srcA_h + (size_t)row2 * Kd + k0_ + j4 * 8;                        \
        cp_async16_s(b_ + (0 * LVL_W + row2 * WROW + j4 * 4) * 4, s0);         \
        cp_async16_s(b_ + (0 * LVL_W + (row2 + 64) * WROW + j4 * 4) * 4,       \
                     s0 + (size_t)64 * Kd);                                    \
        s0 = srcA_l + (size_t)row2 * Kd + k0_ + j4 * 8;                        \
        cp_async16_s(b_ + (1 * LVL_W + row2 * WROW + j4 * 4) * 4, s0);         \
        cp_async16_s(b_ + (1 * LVL_W + (row2 + 64) * WROW + j4 * 4) * 4,       \
                     s0 + (size_t)64 * Kd);                                    \
        s0 = srcB_h + (size_t)row2 * Kd + k0_ + j4 * 8;                        \
        cp_async16_s(b_ + (2 * LVL_W + row2 * WROW + j4 * 4) * 4, s0);         \
        cp_async16_s(b_ + (2 * LVL_W + (row2 + 64) * WROW + j4 * 4) * 4,       \
                     s0 + (size_t)64 * Kd);                                    \
        s0 = srcB_l + (size_t)row2 * Kd + k0_ + j4 * 8;                        \
        cp_async16_s(b_ + (3 * LVL_W + row2 * WROW + j4 * 4) * 4, s0);         \
        cp_async16_s(b_ + (3 * LVL_W + (row2 + 64) * WROW + j4 * 4) * 4,       \
                     s0 + (size_t)64 * Kd);                                    \
        asm volatile("cp.async.commit_group;");                                \
    } while (0)

    ISSUE_CHUNK(0, 0);

    for (int ck = 0; ck < nchunks; ck++) {
        int cur = ck & 1;
        bool has_next = (ck + 1 < nchunks);
        if (has_next) {
            ISSUE_CHUNK(ck + 1, cur ^ 1);
            asm volatile("cp.async.wait_group 1;");
        } else {
            asm volatile("cp.async.wait_group 0;");
        }
        __syncthreads();

        const u32* SAh = sm + cur * BUF_W;
        const u32* SAl = SAh + LVL_W;
        const u32* SBh = SAh + 2 * LVL_W;
        const u32* SBl = SAh + 3 * LVL_W;

#pragma unroll
        for (int ks = 0; ks < 2; ks++) {
            int ko = ks * 8;
            u32 bh[4][2], bl[4][2];
#pragma unroll
            for (int nt = 0; nt < 4; nt++) {
                int rb = (wn + nt * 8 + g) * WROW + ko + t;
                bh[nt][0] = SBh[rb]; bh[nt][1] = SBh[rb + 4];
                bl[nt][0] = SBl[rb]; bl[nt][1] = SBl[rb + 4];
            }
#pragma unroll
            for (int mt = 0; mt < 4; mt++) {
                int r0 = (wm + mt * 16 + g) * WROW + ko + t;
                int r8 = r0 + 8 * WROW;
                u32 ah[4], al[4];
                ah[0] = SAh[r0]; ah[1] = SAh[r8];
                ah[2] = SAh[r0 + 4]; ah[3] = SAh[r8 + 4];
                al[0] = SAl[r0]; al[1] = SAl[r8];
                al[2] = SAl[r0 + 4]; al[3] = SAl[r8 + 4];
#pragma unroll
                for (int nt = 0; nt < 4; nt++) {
                    mma_f16(acc[mt][nt], ah, bh[nt]);   // hi*hi (exact in fp32)
                    mma_f16(acc[mt][nt], ah, bl[nt]);   // hi*lo
                    mma_f16(acc[mt][nt], al, bh[nt]);   // lo*hi
                }
            }
        }
        __syncthreads();
    }

#pragma unroll
    for (int mt = 0; mt < 4; mt++) {
#pragma unroll
        for (int nt = 0; nt < 4; nt++) {
            int r = m0 + wm + mt * 16 + g;
            int c = n0 + wn + nt * 8 + t * 2;
            if (c + 1 < N) {
                *(float2*)(C + (size_t)r * N + c) =
                    make_float2(acc[mt][nt][0], acc[mt][nt][1]);
                *(float2*)(C + (size_t)(r + 8) * N + c) =
                    make_float2(acc[mt][nt][2], acc[mt][nt][3]);
            } else if (c < N) {
                C[(size_t)r * N + c] = acc[mt][nt][0];
                C[(size_t)(r + 8) * N + c] = acc[mt][nt][2];
            }
        }
    }
}

// ---------------- K2: fused conv+silu+norms+expand -> xv, fv, rin, cg ----------------
__global__ __launch_bounds__(256) void convbuild_kernel(const float* __restrict__ conv_w,
                                                        const float* __restrict__ w_in_norm,
                                                        const float* __restrict__ w_f_norm,
                                                        const float* __restrict__ w_r_norm) {
    __shared__ float sy[CONVn];
    __shared__ float sb1[8], sb2[8];
    __shared__ float srs[1];
    int row = blockIdx.x;      // b*S + s
    int s = row % Sn;
    int tid = threadIdx.x;

    const float* p0 = g_proj + (size_t)row * NPROJ;
    for (int c = tid; c < CONVn; c += 256) {
        float w0 = conv_w[c * 4 + 0], w1 = conv_w[c * 4 + 1];
        float w2 = conv_w[c * 4 + 2], w3 = conv_w[c * 4 + 3];
        float acc = w3 * p0[c];
        if (s >= 1) acc += w2 * p0[c - NPROJ];
        if (s >= 2) acc += w1 * p0[c - 2 * NPROJ];
        if (s >= 3) acc += w0 * p0[c - 3 * NPROJ];
        sy[c] = acc * sigmoidf_(acc);
    }
    __syncthreads();

    float s1 = 0.f, s2 = 0.f;
    for (int i = tid; i < 512; i += 256) {
        s1 += sy[i] * sy[i];
        s2 += sy[512 + i] * sy[512 + i];
    }
    float t1 = blk_sum256(s1, sb1);
    float t2 = blk_sum256(s2, sb2);
    if (tid == 0) {
        float sr = 0.f;
#pragma unroll
        for (int h = 0; h < 8; h++) sr += sy[1024 + h] * sy[1024 + h];
        srs[0] = rsqrtf(sr * (1.f / 8.f) + 1e-6f);
    }
    float si = rsqrtf(t1 * (1.f / 512.f) + 1e-6f);
    float sf = rsqrtf(t2 * (1.f / 512.f) + 1e-6f);
    __syncthreads();

    float e0 = sy[1040], e1 = sy[1041];
    float* xv = g_xv + (size_t)row * 1024;
    float* fv = g_fv + (size_t)row * 1024;
#pragma unroll
    for (int q = 0; q < 4; q++) {
        int o = tid + q * 256;
        int hh = o >> 7, rem = o & 127, ee = rem >> 6, dd = rem & 63;
        int ii = hh * 64 + dd;
        float ex = (ee == 0) ? e0 : e1;
        xv[o] = sy[ii] * si * w_in_norm[ii] * ex;
        fv[o] = sy[512 + ii] * sf * w_f_norm[ii] * ex;
    }
    if (tid < 8) {
        g_rin[(size_t)row * 8 + tid] = sy[1024 + tid] * srs[0] * w_r_norm[tid];
        g_cg[(size_t)row * 8 + tid] = sy[1032 + tid];
    }
}

// ---------------- K3: mega kernel — scan (CTAs 0..31) + ugate (CTAs 32..8223) ----------------
// Roles are exclusive per CTA, so the two shared layouts overlay one buffer.
// scan view:  h_sh[2][128] | rh_sh[128] | rin_s[Sn] | cg_s[Sn] | sbuf[8]   (~17.9 KB)
// ugate view: srow[1024]   | suw[64*129]            | sbuf[8]              (~37.2 KB)
struct ScanSmem {
    float h_sh[2][128];
    float rh_sh[128];
    float rin_s[Sn];
    float cg_s[Sn];
    float sbuf[8];
};
struct UgateSmem {
    float srow[1024];
    float suw[64 * 129];
    float sbuf[8];
};
#define MEGA_SMEM_BYTES (sizeof(UgateSmem) > sizeof(ScanSmem) ? sizeof(UgateSmem) : sizeof(ScanSmem))

__global__ __launch_bounds__(256, 1) void scan_ugate_kernel(const float* __restrict__ state_w,
                                                            const float* __restrict__ res_w,
                                                            const float* __restrict__ up_w,
                                                            const float* __restrict__ w_g_norm) {
    __shared__ __align__(16) char smem_u[MEGA_SMEM_BYTES];
    int tid = threadIdx.x;

    if (blockIdx.x < 32) {
        // ================= SCAN role =================
        ScanSmem* S = (ScanSmem*)smem_u;
        int b = blockIdx.x >> 3, hh = blockIdx.x & 7;
        int e = tid >> 1, half = tid & 1;

        const float* bw = state_w + (size_t)hh * 16384 + half * 64 * 128 + e;
        const float* bf = state_w + (size_t)(8 + hh) * 16384 + half * 64 * 128 + e;
        const float* br = state_w + (size_t)(16 + hh) * 16384 + half * 64 * 128 + e;
        float ssW = 0.f, ssF = 0.f, ssR = 0.f;
#pragma unroll 8
        for (int i = 0; i < 64; i++) {
            float vw = bw[i * 128], vf = bf[i * 128], vr = br[i * 128];
            ssW += vw * vw; ssF += vf * vf; ssR += vr * vr;
        }
        float totW = blk_sum256(ssW, S->sbuf);
        float totF = blk_sum256(ssF, S->sbuf);
        float totR = blk_sum256(ssR, S->sbuf);
        float invW = 1.f / fmaxf(sqrtf(totW), 1e-12f);
        float invF = 1.f / fmaxf(sqrtf(totF), 1e-12f);
        float invR = 1.f / fmaxf(sqrtf(totR), 1e-12f);

        ull W2[32], F2[32], R2[32];
#pragma unroll
        for (int i = 0; i < 32; i++) {
            W2[i] = pk2(bw[(2 * i) * 128] * invW, bw[(2 * i + 1) * 128] * invW);
            F2[i] = pk2(bf[(2 * i) * 128] * invF, bf[(2 * i + 1) * 128] * invF);
            R2[i] = pk2(br[(2 * i) * 128] * invR, br[(2 * i + 1) * 128] * invR);
        }

        for (int t = tid; t < Sn; t += 256) {
            S->rin_s[t] = g_rin[(size_t)(b * Sn + t) * 8 + hh];
            S->cg_s[t]  = g_cg[(size_t)(b * Sn + t) * 8 + hh];
        }
        if (tid < 128) S->h_sh[0][tid] = 0.f;
        float resw = res_w[hh];
        size_t rowbase = ((size_t)b * Sn) * 1024 + hh * 128;
        const float* xsrc = g_xv + rowbase + e;
        const float* fsrc = g_fv + rowbase + e;

        float xq[8], fq[8];
#pragma unroll
        for (int s = 0; s < 8; s++) {
            xq[s] = xsrc[(size_t)s * 1024];
            fq[s] = fsrc[(size_t)s * 1024];
        }

        for (int t8 = 0; t8 < Sn / 8; t8++) {
#pragma unroll
            for (int s = 0; s < 8; s++) {
                int t = t8 * 8 + s;
                int cur = t & 1, nxt = cur ^ 1;
                __syncthreads();   // S1

                const ulonglong2* h4 = (const ulonglong2*)(S->h_sh[cur]) + half * 8;
                ull pRa = 0ull, pRb = 0ull;
#pragma unroll
                for (int i = 0; i < 8; i++) {
                    ulonglong2 hv = h4[i];
                    pRa = ffma2(hv.x, R2[2 * i], pRa);
                    pRb = ffma2(hv.y, R2[2 * i + 1], pRb);
                }
                float2 fa = u2f(pRa), fb = u2f(pRb);
                float pR = (fa.x + fa.y) + (fb.x + fb.y);
                pR += __shfl_xor_sync(0xffffffffu, pR, 1);

                float hcur_e = S->h_sh[cur][e];
                if (half == 0) {
                    S->rh_sh[e] = sigmoidf_(S->rin_s[t] + pR) * hcur_e;
                }
                __syncthreads();   // S2

                float xt = xq[s], ft = fq[s];
                {
                    int tp = t + 8;
                    if (tp < Sn) {
                        xq[s] = xsrc[(size_t)tp * 1024];
                        fq[s] = fsrc[(size_t)tp * 1024];
                    }
                }

                const ulonglong2* rh4 = (const ulonglong2*)(S->rh_sh) + half * 8;
                ull pFa = 0ull, pFb = 0ull, pWa = 0ull, pWb = 0ull;
#pragma unroll
                for (int i = 0; i < 8; i++) {
                    ulonglong2 hv = h4[i];
                    ulonglong2 rv = rh4[i];
                    pWa = ffma2(rv.x, W2[2 * i], pWa);
                    pFa = ffma2(hv.x, F2[2 * i], pFa);
                    pWb = ffma2(rv.y, W2[2 * i + 1], pWb);
                    pFb = ffma2(hv.y, F2[2 * i + 1], pFb);
                }
                float2 wa = u2f(pWa), wb = u2f(pWb), ga = u2f(pFa), gb = u2f(pFb);
                float pW = (wa.x + wa.y) + (wb.x + wb.y);
                float pF = (ga.x + ga.y) + (gb.x + gb.y);
                pW += __shfl_xor_sync(0xffffffffu, pW, 1);
                pF += __shfl_xor_sync(0xffffffffu, pF, 1);

                float hn = 0.f;
                if (half == 1) {
                    float fgate = sigmoidf_(ft + pF);
                    float htl = tanhf_(xt + pW);
                    hn = fgate * hcur_e + (1.f - fgate) * htl;
                    S->h_sh[nxt][e] = hn;
                }
                float hn_b = __shfl_xor_sync(0xffffffffu, hn, 1);
                if (half == 0) {
                    g_scan[rowbase + (size_t)t * 1024 + e] = resw * xt + hn_b * S->cg_s[t];
                }
            }
            if ((t8 & 7) == 7) {     // every 64 steps: publish progress
                __threadfence();
                __syncthreads();
                if (tid == 0) atomicAdd(&g_prog[b], 1);
            }
        }
    } else {
        // ================= UGATE role =================
        UgateSmem* U = (UgateSmem*)smem_u;
        int rowid = blockIdx.x - 32;          // 0..8191
        int b = rowid & 3, s = rowid >> 2;    // unlock order matches bid order
        int row = b * Sn + s;

        // preload up_w into smem before waiting
        for (int i = tid; i < 8192; i += 256) {
            int j = i >> 7, d = i & 127;
            U->suw[j * 129 + d] = up_w[i];
        }

        // wait for all 8 heads of batch b to pass step s (bounded spin)
        if (tid == 0) {
            int target = 8 * ((s >> 6) + 1);
            volatile int* pr = &g_prog[b];
            for (long it = 0; it < (1L << 27); it++) {
                if (*pr >= target) break;
            }
        }
        __syncthreads();

        const float* sr = g_scan + (size_t)row * 1024;
        for (int i = tid; i < 1024; i += 256) U->srow[i] = __ldcg(sr + i);
        __syncthreads();

        int o0 = tid * 2, o1 = o0 + 1;
        int hhd = o0 >> 6;
        int j0 = o0 & 63, j1 = o1 & 63;
        const float* a = U->srow + hhd * 128;
        float acc0 = 0.f, acc1 = 0.f;
#pragma unroll 16
        for (int d = 0; d < 128; d++) {
            float av = a[d];
            acc0 += av * U->suw[j0 * 129 + d];
            acc1 += av * U->suw[j1 * 129 + d];
        }
        const float* gptr = g_proj + (size_t)row * NPROJ + CONVn;
        float gA = gptr[o0], gB = gptr[o1];
        float u0 = acc0 * (gA * sigmoidf_(gA));
        float u1 = acc1 * (gB * sigmoidf_(gB));

        float tot = blk_sum256(u0 * u0 + u1 * u1, U->sbuf);
        float scale = rsqrtf(tot * (1.f / 512.f) + 1e-6f);
        float v0 = u0 * scale * w_g_norm[o0];
        float v1 = u1 * scale * w_g_norm[o1];

        size_t ob = (size_t)row * 512;
        __half h0 = __float2half_rn(v0), h1 = __float2half_rn(v1);
        g_vh[ob + o0] = h0;
        g_vh[ob + o1] = h1;
        g_vl[ob + o0] = __float2half_rn(v0 - __half2float(h0));
        g_vl[ob + o1] = __float2half_rn(v1 - __half2float(h1));
    }
}

// ---------------- launch ----------------
extern "C" void kernel_launch(void* const* d_in, const int* in_sizes, int n_in,
                              void* d_out, int out_size) {
    const float* x         = (const float*)d_in[0];
    const float* w_in      = (const float*)d_in[1];
    const float* conv_w    = (const float*)d_in[2];
    const float* state_w   = (const float*)d_in[3];
    const float* up_w      = (const float*)d_in[4];
    const float* out_w     = (const float*)d_in[5];
    const float* res_w     = (const float*)d_in[6];
    const float* w_in_norm = (const float*)d_in[7];
    const float* w_f_norm  = (const float*)d_in[8];
    const float* w_r_norm  = (const float*)d_in[9];
    const float* w_g_norm  = (const float*)d_in[10];
    float* out = (float*)d_out;

    float* p_proj = nullptr;
    cudaGetSymbolAddress((void**)&p_proj, g_proj);
    __half *p_xh, *p_xl, *p_wh, *p_wl, *p_owh, *p_owl, *p_vh, *p_vl;
    cudaGetSymbolAddress((void**)&p_xh, g_xh);
    cudaGetSymbolAddress((void**)&p_xl, g_xl);
    cudaGetSymbolAddress((void**)&p_wh, g_wh);
    cudaGetSymbolAddress((void**)&p_wl, g_wl);
    cudaGetSymbolAddress((void**)&p_owh, g_owh);
    cudaGetSymbolAddress((void**)&p_owl, g_owl);
    cudaGetSymbolAddress((void**)&p_vh, g_vh);
    cudaGetSymbolAddress((void**)&p_vl, g_vl);

    cudaFuncSetAttribute(h2s_gemm_nt, cudaFuncAttributeMaxDynamicSharedMemorySize,
                         TC_SMEM_DYN);

    // #1: all operand splits (+ progress reset)
    cvt_all_kernel<<<(NX + NW + NO + 255) / 256, 256>>>(x, w_in, out_w);
    // #2: proj = x @ w_in^T
    h2s_gemm_nt<<<dim3(NPPAD / TCN, BSn / TCM), 256, TC_SMEM_DYN>>>(
        p_xh, p_xl, p_wh, p_wl, p_proj, BSn, NPROJ, Dn);
    // #3: fused conv+silu+norms+expand
    convbuild_kernel<<<BSn, 256>>>(conv_w, w_in_norm, w_f_norm, w_r_norm);
    // #4: mega — scan (32 CTAs) + overlapped ugate (8192 CTAs)
    scan_ugate_kernel<<<32 + BSn, 256>>>(state_w, res_w, up_w, w_g_norm);
    // #5: final = v @ out_w^T
    h2s_gemm_nt<<<dim3(Dn / TCN, BSn / TCM), 256, TC_SMEM_DYN>>>(
        p_vh, p_vl, p_owh, p_owl, out, BSn, Dn, LRn);
}